// round 1
// baseline (speedup 1.0000x reference)
#include <cuda_runtime.h>

#define NN 16384
#define EE 393216
#define EF (EE + NN)      // 409600 edges incl. self loops
#define GG 256
#define HIDN 128
#define NHEAD 4
#define HC 32
#define NLAY 8
#define NDIM 21
#define EDIM 6

// ---------------- scratch (device globals; no allocation allowed) ----------
__device__ float g_bufA[NN * HIDN];
__device__ float g_bufB[NN * HIDN];
__device__ float g_xl[NN * HIDN];
__device__ float g_xr[NN * HIDN];
__device__ float g_conv[NN * HIDN];
__device__ float g_loop_attr[NN * EDIM];
__device__ float g_loop_sum[NN * EDIM];
__device__ int   g_deg[NN];
__device__ int   g_rowoff[NN + 1];
__device__ int   g_cursor[NN];
__device__ int   g_csr_src[EF];
__device__ int   g_csr_eid[EF];
__device__ float g_s[EF * NHEAD];
__device__ float g_stats[NLAY * 2 * HIDN];
__device__ float g_pooled[GG * HIDN];
__device__ float g_gcnt[GG];

// ---------------- init: zero everything that gets atomically accumulated ---
__global__ void k_init() {
    int i = blockIdx.x * blockDim.x + threadIdx.x;
    int stride = gridDim.x * blockDim.x;
    for (int j = i; j < NN * EDIM; j += stride) g_loop_sum[j] = 0.f;
    for (int j = i; j < NN; j += stride) { g_deg[j] = 0; g_cursor[j] = 0; }
    for (int j = i; j < NLAY * 2 * HIDN; j += stride) g_stats[j] = 0.f;
    for (int j = i; j < GG * HIDN; j += stride) g_pooled[j] = 0.f;
    for (int j = i; j < GG; j += stride) g_gcnt[j] = 0.f;
}

// ---------------- degree + self-loop attr accumulation ---------------------
__global__ void k_deg_loop(const int* __restrict__ ei, const float* __restrict__ ea) {
    int e = blockIdx.x * blockDim.x + threadIdx.x;
    if (e >= EE) return;
    int d = ei[EE + e];
    atomicAdd(&g_deg[d], 1);
#pragma unroll
    for (int k = 0; k < EDIM; k++)
        atomicAdd(&g_loop_sum[d * EDIM + k], ea[e * EDIM + k]);
}

__global__ void k_loopattr() {
    int n = blockIdx.x * blockDim.x + threadIdx.x;
    if (n >= NN) return;
    float inv = 1.0f / fmaxf((float)g_deg[n], 1.0f);
#pragma unroll
    for (int k = 0; k < EDIM; k++)
        g_loop_attr[n * EDIM + k] = g_loop_sum[n * EDIM + k] * inv;
}

// ---------------- exclusive scan of (deg+1) --> CSR row offsets ------------
__global__ void k_scan() {
    __shared__ int blk[1024];
    int t = threadIdx.x;
    int base = t * 16;
    int loc[16];
    int run = 0;
#pragma unroll
    for (int j = 0; j < 16; j++) { loc[j] = run; run += g_deg[base + j] + 1; }
    blk[t] = run;
    __syncthreads();
    for (int off = 1; off < 1024; off <<= 1) {
        int v = (t >= off) ? blk[t - off] : 0;
        __syncthreads();
        blk[t] += v;
        __syncthreads();
    }
    int excl = (t == 0) ? 0 : blk[t - 1];
#pragma unroll
    for (int j = 0; j < 16; j++) g_rowoff[base + j] = excl + loc[j];
    if (t == 1023) g_rowoff[NN] = blk[1023];
}

// ---------------- scatter edges (incl self-loops) into dst-sorted CSR ------
__global__ void k_scatter(const int* __restrict__ ei) {
    int t = blockIdx.x * blockDim.x + threadIdx.x;
    if (t >= EF) return;
    int s, d;
    if (t < EE) { s = ei[t]; d = ei[EE + t]; }
    else        { s = t - EE; d = s; }
    int pos = g_rowoff[d] + atomicAdd(&g_cursor[d], 1);
    g_csr_src[pos] = s;
    g_csr_eid[pos] = t;
}

// ---------------- input projection: h = relu(x @ Win + b_in) ---------------
__global__ void k_ingemm(const float* __restrict__ x, const float* __restrict__ Win,
                         const float* __restrict__ b_in) {
    __shared__ float xs[NDIM];
    int n = blockIdx.x;
    int f = threadIdx.x;
    if (f < NDIM) xs[f] = x[n * NDIM + f];
    __syncthreads();
    float a = b_in[f];
#pragma unroll
    for (int k = 0; k < NDIM; k++) a += xs[k] * Win[k * HIDN + f];
    g_bufA[n * HIDN + f] = fmaxf(a, 0.f);
}

// ---------------- dual GEMM: xl = h@Wl+bl, xr = h@Wr+br --------------------
#define BM 32
__global__ void k_gemm_lr(const float* __restrict__ in,
                          const float* __restrict__ Wl, const float* __restrict__ bl,
                          const float* __restrict__ Wr, const float* __restrict__ br) {
    __shared__ float sh[BM][HIDN];
    int n0 = blockIdx.x * BM;
    int f = threadIdx.x;
#pragma unroll
    for (int m = 0; m < BM; m++) sh[m][f] = in[(n0 + m) * HIDN + f];
    __syncthreads();
    float al[BM], ar[BM];
#pragma unroll
    for (int m = 0; m < BM; m++) { al[m] = 0.f; ar[m] = 0.f; }
    for (int k = 0; k < HIDN; k++) {
        float wl = Wl[k * HIDN + f];
        float wr = Wr[k * HIDN + f];
#pragma unroll
        for (int m = 0; m < BM; m++) {
            float hv = sh[m][k];
            al[m] += hv * wl;
            ar[m] += hv * wr;
        }
    }
    float blv = bl[f], brv = br[f];
#pragma unroll
    for (int m = 0; m < BM; m++) {
        g_xl[(n0 + m) * HIDN + f] = al[m] + blv;
        g_xr[(n0 + m) * HIDN + f] = ar[m] + brv;
    }
}

// ---------------- edge attention scores (warp per edge) --------------------
__global__ void k_score(const int* __restrict__ ei, const float* __restrict__ ea,
                        const float* __restrict__ We_l, const float* __restrict__ att_l) {
    __shared__ float Wes[EDIM * HIDN];
    __shared__ float atts[HIDN];
    int t = threadIdx.x;
    for (int j = t; j < EDIM * HIDN; j += blockDim.x) Wes[j] = We_l[j];
    if (t < HIDN) atts[t] = att_l[t];
    __syncthreads();

    int lane = t & 31;
    int e = blockIdx.x * (blockDim.x >> 5) + (t >> 5);
    if (e >= EF) return;

    int s, d;
    const float* eap;
    if (e < EE) { s = ei[e]; d = ei[EE + e]; eap = ea + (long)e * EDIM; }
    else        { int n = e - EE; s = n; d = n; eap = g_loop_attr + (long)n * EDIM; }

    float ear[EDIM];
#pragma unroll
    for (int k = 0; k < EDIM; k++) ear[k] = __ldg(&eap[k]);

    const float* xls = g_xl + (long)s * HIDN;
    const float* xrd = g_xr + (long)d * HIDN;
#pragma unroll
    for (int h = 0; h < NHEAD; h++) {
        int f = h * HC + lane;
        float ee = 0.f;
#pragma unroll
        for (int k = 0; k < EDIM; k++) ee += ear[k] * Wes[k * HIDN + f];
        float m = xls[f] + xrd[f] + ee;
        m = (m > 0.f) ? m : 0.2f * m;
        float p = m * atts[f];
#pragma unroll
        for (int off = 16; off > 0; off >>= 1)
            p += __shfl_xor_sync(0xffffffffu, p, off);
        if (lane == h) g_s[(long)e * NHEAD + h] = p;
    }
}

// ---------------- per-node softmax + aggregation (warp per node) -----------
__global__ void k_agg(const float* __restrict__ bconv_l) {
    int lane = threadIdx.x & 31;
    int i = blockIdx.x * (blockDim.x >> 5) + (threadIdx.x >> 5);
    if (i >= NN) return;
    int beg = g_rowoff[i], end = g_rowoff[i + 1];

    float mx0 = -1e30f, mx1 = -1e30f, mx2 = -1e30f, mx3 = -1e30f;
    for (int j = beg + lane; j < end; j += 32) {
        float4 sv = ((const float4*)g_s)[g_csr_eid[j]];
        mx0 = fmaxf(mx0, sv.x); mx1 = fmaxf(mx1, sv.y);
        mx2 = fmaxf(mx2, sv.z); mx3 = fmaxf(mx3, sv.w);
    }
#pragma unroll
    for (int off = 16; off > 0; off >>= 1) {
        mx0 = fmaxf(mx0, __shfl_xor_sync(0xffffffffu, mx0, off));
        mx1 = fmaxf(mx1, __shfl_xor_sync(0xffffffffu, mx1, off));
        mx2 = fmaxf(mx2, __shfl_xor_sync(0xffffffffu, mx2, off));
        mx3 = fmaxf(mx3, __shfl_xor_sync(0xffffffffu, mx3, off));
    }
    float dn0 = 0.f, dn1 = 0.f, dn2 = 0.f, dn3 = 0.f;
    for (int j = beg + lane; j < end; j += 32) {
        float4 sv = ((const float4*)g_s)[g_csr_eid[j]];
        dn0 += __expf(sv.x - mx0); dn1 += __expf(sv.y - mx1);
        dn2 += __expf(sv.z - mx2); dn3 += __expf(sv.w - mx3);
    }
#pragma unroll
    for (int off = 16; off > 0; off >>= 1) {
        dn0 += __shfl_xor_sync(0xffffffffu, dn0, off);
        dn1 += __shfl_xor_sync(0xffffffffu, dn1, off);
        dn2 += __shfl_xor_sync(0xffffffffu, dn2, off);
        dn3 += __shfl_xor_sync(0xffffffffu, dn3, off);
    }
    float id0 = 1.0f / dn0, id1 = 1.0f / dn1, id2 = 1.0f / dn2, id3 = 1.0f / dn3;

    float a0 = 0.f, a1 = 0.f, a2 = 0.f, a3 = 0.f;
    for (int j = beg; j < end; j++) {
        int eid = g_csr_eid[j];
        int sn = g_csr_src[j];
        float wl = 0.f;
        if (lane < 4) {
            float sv = g_s[(long)eid * NHEAD + lane];
            float mxl = (lane == 0) ? mx0 : (lane == 1) ? mx1 : (lane == 2) ? mx2 : mx3;
            float idl = (lane == 0) ? id0 : (lane == 1) ? id1 : (lane == 2) ? id2 : id3;
            wl = __expf(sv - mxl) * idl;
        }
        float w0 = __shfl_sync(0xffffffffu, wl, 0);
        float w1 = __shfl_sync(0xffffffffu, wl, 1);
        float w2 = __shfl_sync(0xffffffffu, wl, 2);
        float w3 = __shfl_sync(0xffffffffu, wl, 3);
        const float* xs = g_xl + (long)sn * HIDN;
        a0 += w0 * xs[lane];
        a1 += w1 * xs[32 + lane];
        a2 += w2 * xs[64 + lane];
        a3 += w3 * xs[96 + lane];
    }
    g_conv[(long)i * HIDN + lane]      = a0 + bconv_l[lane];
    g_conv[(long)i * HIDN + 32 + lane] = a1 + bconv_l[32 + lane];
    g_conv[(long)i * HIDN + 64 + lane] = a2 + bconv_l[64 + lane];
    g_conv[(long)i * HIDN + 96 + lane] = a3 + bconv_l[96 + lane];
}

// ---------------- batchnorm stats (sum, sumsq per feature) -----------------
__global__ void k_bnstats(int l) {
    __shared__ float ssum[HIDN];
    __shared__ float ssq[HIDN];
    int t = threadIdx.x;
    for (int j = t; j < HIDN; j += blockDim.x) { ssum[j] = 0.f; ssq[j] = 0.f; }
    __syncthreads();
    int idx = blockIdx.x * blockDim.x + t;
    int stride = gridDim.x * blockDim.x;
    for (int j = idx; j < NN * HIDN; j += stride) {
        float v = g_conv[j];
        int f = j & (HIDN - 1);
        atomicAdd(&ssum[f], v);
        atomicAdd(&ssq[f], v * v);
    }
    __syncthreads();
    for (int j = t; j < HIDN; j += blockDim.x) {
        atomicAdd(&g_stats[l * 2 * HIDN + j], ssum[j]);
        atomicAdd(&g_stats[l * 2 * HIDN + HIDN + j], ssq[j]);
    }
}

// ---------------- batchnorm apply (+ optional residual) + relu -------------
__global__ void k_bnapply(const float* __restrict__ gamma_l, const float* __restrict__ beta_l,
                          const float* __restrict__ res, float* __restrict__ out, int l) {
    int idx = blockIdx.x * blockDim.x + threadIdx.x;
    int stride = gridDim.x * blockDim.x;
    const float invN = 1.0f / (float)NN;
    for (int j = idx; j < NN * HIDN; j += stride) {
        int f = j & (HIDN - 1);
        float sum = g_stats[l * 2 * HIDN + f];
        float sq  = g_stats[l * 2 * HIDN + HIDN + f];
        float mean = sum * invN;
        float var = sq * invN - mean * mean;
        float istd = rsqrtf(var + 1e-5f);
        float y = gamma_l[f] * (g_conv[j] - mean) * istd + beta_l[f];
        if (res) y += res[j];
        out[j] = fmaxf(y, 0.f);
    }
}

// ---------------- mean pooling per graph -----------------------------------
__global__ void k_pool(const int* __restrict__ batch) {
    int idx = blockIdx.x * blockDim.x + threadIdx.x;
    int stride = gridDim.x * blockDim.x;
    for (int j = idx; j < NN * HIDN; j += stride) {
        int n = j >> 7;
        int f = j & (HIDN - 1);
        atomicAdd(&g_pooled[batch[n] * HIDN + f], g_bufA[j]);
    }
    for (int j = idx; j < NN; j += stride)
        atomicAdd(&g_gcnt[batch[j]], 1.0f);
}

// ---------------- final MLP: relu(pooled@W1+b1)@W2+b2 ----------------------
__global__ void k_mlp(const float* __restrict__ W1, const float* __restrict__ b1,
                      const float* __restrict__ W2, const float* __restrict__ b2,
                      float* __restrict__ out) {
    __shared__ float pl[HIDN];
    __shared__ float hid[64];
    int g = blockIdx.x;
    int t = threadIdx.x;
    float inv = 1.0f / fmaxf(g_gcnt[g], 1.0f);
    for (int j = t; j < HIDN; j += 64) pl[j] = g_pooled[g * HIDN + j] * inv;
    __syncthreads();
    float a = b1[t];
    for (int k = 0; k < HIDN; k++) a += pl[k] * W1[k * 64 + t];
    hid[t] = fmaxf(a, 0.f);
    __syncthreads();
    if (t < 3) {
        float lg = b2[t];
        for (int k = 0; k < 64; k++) lg += hid[k] * W2[k * 3 + t];
        out[g * 3 + t] = lg;
    }
}

// ---------------- launch ----------------------------------------------------
extern "C" void kernel_launch(void* const* d_in, const int* in_sizes, int n_in,
                              void* d_out, int out_size) {
    const float* x     = (const float*)d_in[0];
    const int*   ei    = (const int*)d_in[1];
    const float* ea    = (const float*)d_in[2];
    const int*   batch = (const int*)d_in[3];
    const float* Win   = (const float*)d_in[4];
    const float* b_in  = (const float*)d_in[5];
    const float* Wl    = (const float*)d_in[6];
    const float* bl    = (const float*)d_in[7];
    const float* Wr    = (const float*)d_in[8];
    const float* br    = (const float*)d_in[9];
    const float* We    = (const float*)d_in[10];
    const float* att   = (const float*)d_in[11];
    const float* bconv = (const float*)d_in[12];
    const float* gamma = (const float*)d_in[13];
    const float* beta  = (const float*)d_in[14];
    const float* W1    = (const float*)d_in[15];
    const float* b1    = (const float*)d_in[16];
    const float* W2    = (const float*)d_in[17];
    const float* b2    = (const float*)d_in[18];
    float* out = (float*)d_out;

    float* bufA = nullptr;
    float* bufB = nullptr;
    cudaGetSymbolAddress((void**)&bufA, g_bufA);
    cudaGetSymbolAddress((void**)&bufB, g_bufB);

    k_init<<<256, 256>>>();
    k_deg_loop<<<(EE + 255) / 256, 256>>>(ei, ea);
    k_loopattr<<<(NN + 255) / 256, 256>>>();
    k_scan<<<1, 1024>>>();
    k_scatter<<<(EF + 255) / 256, 256>>>(ei);
    k_ingemm<<<NN, HIDN>>>(x, Win, b_in);

    for (int l = 0; l < NLAY; l++) {
        const float* in  = (l % 2 == 0) ? bufA : bufB;
        float* outb      = (l % 2 == 0) ? bufB : bufA;
        const float* res = (l % 2 == 0) ? nullptr : bufA;  // odd layer: residual = old bufA

        k_gemm_lr<<<NN / BM, HIDN>>>(in,
                                     Wl + (size_t)l * HIDN * HIDN, bl + (size_t)l * HIDN,
                                     Wr + (size_t)l * HIDN * HIDN, br + (size_t)l * HIDN);
        k_score<<<(EF + 7) / 8, 256>>>(ei, ea,
                                       We + (size_t)l * EDIM * HIDN,
                                       att + (size_t)l * NHEAD * HC);
        k_agg<<<NN / 8, 256>>>(bconv + (size_t)l * HIDN);
        k_bnstats<<<512, 256>>>(l);
        k_bnapply<<<2048, 256>>>(gamma + (size_t)l * HIDN, beta + (size_t)l * HIDN,
                                 res, outb, l);
    }

    k_pool<<<1024, 256>>>(batch);
    k_mlp<<<GG, 64>>>(W1, b1, W2, b2, out);
}

// round 2
// speedup vs baseline: 1.4289x; 1.4289x over previous
#include <cuda_runtime.h>

#define NN 16384
#define EE 393216
#define EF (EE + NN)      // 409600 edges incl. self loops
#define GG 256
#define HIDN 128
#define NHEAD 4
#define HC 32
#define NLAY 8
#define NDIM 21
#define EDIM 6

// ---------------- scratch (device globals; no allocation allowed) ----------
__device__ float g_bufA[NN * HIDN];
__device__ float g_bufB[NN * HIDN];
__device__ float g_xl[NN * HIDN];
__device__ float g_xr[NN * HIDN];
__device__ float g_conv[NN * HIDN];
__device__ float g_loop_attr[NN * EDIM];
__device__ float g_loop_sum[NN * EDIM];
__device__ int   g_deg[NN];
__device__ int   g_rowoff[NN + 1];
__device__ int   g_cursor[NN];
__device__ int   g_csr_src[EF];
__device__ float g_ea_csr[(size_t)EF * EDIM];
__device__ float g_stats[NLAY * 2 * HIDN];
__device__ float g_pooled[GG * HIDN];
__device__ float g_gcnt[GG];

// ---------------- init: zero everything that gets atomically accumulated ---
__global__ void k_init() {
    int i = blockIdx.x * blockDim.x + threadIdx.x;
    int stride = gridDim.x * blockDim.x;
    for (int j = i; j < NN * EDIM; j += stride) g_loop_sum[j] = 0.f;
    for (int j = i; j < NN; j += stride) { g_deg[j] = 0; g_cursor[j] = 0; }
    for (int j = i; j < NLAY * 2 * HIDN; j += stride) g_stats[j] = 0.f;
    for (int j = i; j < GG * HIDN; j += stride) g_pooled[j] = 0.f;
    for (int j = i; j < GG; j += stride) g_gcnt[j] = 0.f;
}

// ---------------- degree + self-loop attr accumulation ---------------------
__global__ void k_deg_loop(const int* __restrict__ ei, const float* __restrict__ ea) {
    int e = blockIdx.x * blockDim.x + threadIdx.x;
    if (e >= EE) return;
    int d = ei[EE + e];
    atomicAdd(&g_deg[d], 1);
#pragma unroll
    for (int k = 0; k < EDIM; k++)
        atomicAdd(&g_loop_sum[d * EDIM + k], ea[e * EDIM + k]);
}

__global__ void k_loopattr() {
    int n = blockIdx.x * blockDim.x + threadIdx.x;
    if (n >= NN) return;
    float inv = 1.0f / fmaxf((float)g_deg[n], 1.0f);
#pragma unroll
    for (int k = 0; k < EDIM; k++)
        g_loop_attr[n * EDIM + k] = g_loop_sum[n * EDIM + k] * inv;
}

// ---------------- exclusive scan of (deg+1) --> CSR row offsets ------------
__global__ void k_scan() {
    __shared__ int blk[1024];
    int t = threadIdx.x;
    int base = t * 16;
    int4 d0 = ((const int4*)g_deg)[t * 4 + 0];
    int4 d1 = ((const int4*)g_deg)[t * 4 + 1];
    int4 d2 = ((const int4*)g_deg)[t * 4 + 2];
    int4 d3 = ((const int4*)g_deg)[t * 4 + 3];
    int dv[16] = {d0.x, d0.y, d0.z, d0.w, d1.x, d1.y, d1.z, d1.w,
                  d2.x, d2.y, d2.z, d2.w, d3.x, d3.y, d3.z, d3.w};
    int loc[16];
    int run = 0;
#pragma unroll
    for (int j = 0; j < 16; j++) { loc[j] = run; run += dv[j] + 1; }
    blk[t] = run;
    __syncthreads();
    for (int off = 1; off < 1024; off <<= 1) {
        int v = (t >= off) ? blk[t - off] : 0;
        __syncthreads();
        blk[t] += v;
        __syncthreads();
    }
    int excl = (t == 0) ? 0 : blk[t - 1];
#pragma unroll
    for (int j = 0; j < 16; j++) g_rowoff[base + j] = excl + loc[j];
    if (t == 1023) g_rowoff[NN] = blk[1023];
}

// ---------------- scatter edges into dst-sorted CSR + gather edge attrs ----
__global__ void k_scatter(const int* __restrict__ ei, const float* __restrict__ ea) {
    int t = blockIdx.x * blockDim.x + threadIdx.x;
    if (t >= EF) return;
    int s, d;
    const float* eap;
    if (t < EE) { s = ei[t]; d = ei[EE + t]; eap = ea + (size_t)t * EDIM; }
    else        { s = t - EE; d = s; eap = g_loop_attr + (size_t)s * EDIM; }
    int pos = g_rowoff[d] + atomicAdd(&g_cursor[d], 1);
    g_csr_src[pos] = s;
    float* dst = g_ea_csr + (size_t)pos * EDIM;
#pragma unroll
    for (int k = 0; k < EDIM; k++) dst[k] = eap[k];
}

// ---------------- input projection: h = relu(x @ Win + b_in) ---------------
__global__ void k_ingemm(const float* __restrict__ x, const float* __restrict__ Win,
                         const float* __restrict__ b_in) {
    __shared__ float xs[NDIM];
    int n = blockIdx.x;
    int f = threadIdx.x;
    if (f < NDIM) xs[f] = x[n * NDIM + f];
    __syncthreads();
    float a = b_in[f];
#pragma unroll
    for (int k = 0; k < NDIM; k++) a += xs[k] * Win[k * HIDN + f];
    g_bufA[n * HIDN + f] = fmaxf(a, 0.f);
}

// ---------------- dual GEMM: xl = h@Wl+bl, xr = h@Wr+br --------------------
#define BM 32
__global__ void k_gemm_lr(const float* __restrict__ in,
                          const float* __restrict__ Wl, const float* __restrict__ bl,
                          const float* __restrict__ Wr, const float* __restrict__ br) {
    __shared__ float sh[BM][HIDN];
    int n0 = blockIdx.x * BM;
    int f = threadIdx.x;
#pragma unroll
    for (int m = 0; m < BM; m++) sh[m][f] = in[(n0 + m) * HIDN + f];
    __syncthreads();
    float al[BM], ar[BM];
#pragma unroll
    for (int m = 0; m < BM; m++) { al[m] = 0.f; ar[m] = 0.f; }
    for (int k = 0; k < HIDN; k++) {
        float wl = Wl[k * HIDN + f];
        float wr = Wr[k * HIDN + f];
#pragma unroll
        for (int m = 0; m < BM; m++) {
            float hv = sh[m][k];
            al[m] += hv * wl;
            ar[m] += hv * wr;
        }
    }
    float blv = bl[f], brv = br[f];
#pragma unroll
    for (int m = 0; m < BM; m++) {
        g_xl[(n0 + m) * HIDN + f] = al[m] + blv;
        g_xr[(n0 + m) * HIDN + f] = ar[m] + brv;
    }
}

// ---------------- fused score + online-softmax + aggregation ---------------
// warp per node; single pass over incident edges (dst-sorted CSR)
__global__ void k_fused(const float* __restrict__ We_l, const float* __restrict__ att_l,
                        const float* __restrict__ bconv_l) {
    int lane = threadIdx.x & 31;
    int node = blockIdx.x * 8 + (threadIdx.x >> 5);

    // cache We columns for this lane's 4 channels (one per head) in registers
    float w0[EDIM], w1[EDIM], w2[EDIM], w3[EDIM];
#pragma unroll
    for (int k = 0; k < EDIM; k++) {
        w0[k] = __ldg(&We_l[k * HIDN + lane]);
        w1[k] = __ldg(&We_l[k * HIDN + 32 + lane]);
        w2[k] = __ldg(&We_l[k * HIDN + 64 + lane]);
        w3[k] = __ldg(&We_l[k * HIDN + 96 + lane]);
    }
    float at0 = __ldg(&att_l[lane]);
    float at1 = __ldg(&att_l[32 + lane]);
    float at2 = __ldg(&att_l[64 + lane]);
    float at3 = __ldg(&att_l[96 + lane]);

    const float* xr = g_xr + (size_t)node * HIDN;
    float xr0 = xr[lane], xr1 = xr[32 + lane], xr2 = xr[64 + lane], xr3 = xr[96 + lane];

    int beg = g_rowoff[node], end = g_rowoff[node + 1];

    float m0 = -1e30f, m1 = -1e30f, m2 = -1e30f, m3 = -1e30f;
    float d0 = 0.f, d1 = 0.f, d2 = 0.f, d3 = 0.f;
    float a0 = 0.f, a1 = 0.f, a2 = 0.f, a3 = 0.f;

    for (int j = beg; j < end; j++) {
        int sn = g_csr_src[j];
        const float2* eap = (const float2*)(g_ea_csr + (size_t)j * EDIM);
        float2 e0 = eap[0], e1 = eap[1], e2 = eap[2];
        const float* xl = g_xl + (size_t)sn * HIDN;
        float xl0 = xl[lane], xl1 = xl[32 + lane], xl2 = xl[64 + lane], xl3 = xl[96 + lane];

        float ee0 = e0.x*w0[0] + e0.y*w0[1] + e1.x*w0[2] + e1.y*w0[3] + e2.x*w0[4] + e2.y*w0[5];
        float ee1 = e0.x*w1[0] + e0.y*w1[1] + e1.x*w1[2] + e1.y*w1[3] + e2.x*w1[4] + e2.y*w1[5];
        float ee2 = e0.x*w2[0] + e0.y*w2[1] + e1.x*w2[2] + e1.y*w2[3] + e2.x*w2[4] + e2.y*w2[5];
        float ee3 = e0.x*w3[0] + e0.y*w3[1] + e1.x*w3[2] + e1.y*w3[3] + e2.x*w3[4] + e2.y*w3[5];

        float t0 = xl0 + xr0 + ee0; t0 = (t0 > 0.f) ? t0 : 0.2f * t0;
        float t1 = xl1 + xr1 + ee1; t1 = (t1 > 0.f) ? t1 : 0.2f * t1;
        float t2 = xl2 + xr2 + ee2; t2 = (t2 > 0.f) ? t2 : 0.2f * t2;
        float t3 = xl3 + xr3 + ee3; t3 = (t3 > 0.f) ? t3 : 0.2f * t3;

        float s0 = t0 * at0, s1 = t1 * at1, s2 = t2 * at2, s3 = t3 * at3;
#pragma unroll
        for (int off = 16; off > 0; off >>= 1) {
            s0 += __shfl_xor_sync(0xffffffffu, s0, off);
            s1 += __shfl_xor_sync(0xffffffffu, s1, off);
            s2 += __shfl_xor_sync(0xffffffffu, s2, off);
            s3 += __shfl_xor_sync(0xffffffffu, s3, off);
        }

        // online softmax update (warp-uniform branches; new-max path is rare)
        if (s0 > m0) { float r = __expf(m0 - s0); a0 = a0 * r + xl0; d0 = d0 * r + 1.f; m0 = s0; }
        else         { float w = __expf(s0 - m0); a0 += w * xl0; d0 += w; }
        if (s1 > m1) { float r = __expf(m1 - s1); a1 = a1 * r + xl1; d1 = d1 * r + 1.f; m1 = s1; }
        else         { float w = __expf(s1 - m1); a1 += w * xl1; d1 += w; }
        if (s2 > m2) { float r = __expf(m2 - s2); a2 = a2 * r + xl2; d2 = d2 * r + 1.f; m2 = s2; }
        else         { float w = __expf(s2 - m2); a2 += w * xl2; d2 += w; }
        if (s3 > m3) { float r = __expf(m3 - s3); a3 = a3 * r + xl3; d3 = d3 * r + 1.f; m3 = s3; }
        else         { float w = __expf(s3 - m3); a3 += w * xl3; d3 += w; }
    }

    float i0 = 1.f / d0, i1 = 1.f / d1, i2 = 1.f / d2, i3 = 1.f / d3;
    size_t o = (size_t)node * HIDN;
    g_conv[o + lane]      = a0 * i0 + bconv_l[lane];
    g_conv[o + 32 + lane] = a1 * i1 + bconv_l[32 + lane];
    g_conv[o + 64 + lane] = a2 * i2 + bconv_l[64 + lane];
    g_conv[o + 96 + lane] = a3 * i3 + bconv_l[96 + lane];
}

// ---------------- batchnorm stats: register-accumulated, atomic-light ------
__global__ void k_bnstats(int l) {
    int f = threadIdx.x;          // 128 threads: one feature each
    int n0 = blockIdx.x * 64;     // 256 blocks x 64 nodes
    float s = 0.f, q = 0.f;
#pragma unroll 4
    for (int n = 0; n < 64; n++) {
        float v = g_conv[(size_t)(n0 + n) * HIDN + f];
        s += v;
        q += v * v;
    }
    atomicAdd(&g_stats[l * 2 * HIDN + f], s);
    atomicAdd(&g_stats[l * 2 * HIDN + HIDN + f], q);
}

// ---------------- batchnorm apply (+ optional residual) + relu -------------
__global__ void k_bnapply(const float* __restrict__ gamma_l, const float* __restrict__ beta_l,
                          const float* __restrict__ res, float* __restrict__ out, int l) {
    int idx = blockIdx.x * blockDim.x + threadIdx.x;
    int stride = gridDim.x * blockDim.x;
    const float invN = 1.0f / (float)NN;
    for (int j = idx; j < NN * HIDN; j += stride) {
        int f = j & (HIDN - 1);
        float sum = g_stats[l * 2 * HIDN + f];
        float sq  = g_stats[l * 2 * HIDN + HIDN + f];
        float mean = sum * invN;
        float var = sq * invN - mean * mean;
        float istd = rsqrtf(var + 1e-5f);
        float y = gamma_l[f] * (g_conv[j] - mean) * istd + beta_l[f];
        if (res) y += res[j];
        out[j] = fmaxf(y, 0.f);
    }
}

// ---------------- mean pooling per graph -----------------------------------
__global__ void k_pool(const int* __restrict__ batch) {
    int idx = blockIdx.x * blockDim.x + threadIdx.x;
    int stride = gridDim.x * blockDim.x;
    for (int j = idx; j < NN * HIDN; j += stride) {
        int n = j >> 7;
        int f = j & (HIDN - 1);
        atomicAdd(&g_pooled[batch[n] * HIDN + f], g_bufA[j]);
    }
    for (int j = idx; j < NN; j += stride)
        atomicAdd(&g_gcnt[batch[j]], 1.0f);
}

// ---------------- final MLP: relu(pooled@W1+b1)@W2+b2 ----------------------
__global__ void k_mlp(const float* __restrict__ W1, const float* __restrict__ b1,
                      const float* __restrict__ W2, const float* __restrict__ b2,
                      float* __restrict__ out) {
    __shared__ float pl[HIDN];
    __shared__ float hid[64];
    int g = blockIdx.x;
    int t = threadIdx.x;
    float inv = 1.0f / fmaxf(g_gcnt[g], 1.0f);
    for (int j = t; j < HIDN; j += 64) pl[j] = g_pooled[g * HIDN + j] * inv;
    __syncthreads();
    float a = b1[t];
    for (int k = 0; k < HIDN; k++) a += pl[k] * W1[k * 64 + t];
    hid[t] = fmaxf(a, 0.f);
    __syncthreads();
    if (t < 3) {
        float lg = b2[t];
        for (int k = 0; k < 64; k++) lg += hid[k] * W2[k * 3 + t];
        out[g * 3 + t] = lg;
    }
}

// ---------------- launch ----------------------------------------------------
extern "C" void kernel_launch(void* const* d_in, const int* in_sizes, int n_in,
                              void* d_out, int out_size) {
    const float* x     = (const float*)d_in[0];
    const int*   ei    = (const int*)d_in[1];
    const float* ea    = (const float*)d_in[2];
    const int*   batch = (const int*)d_in[3];
    const float* Win   = (const float*)d_in[4];
    const float* b_in  = (const float*)d_in[5];
    const float* Wl    = (const float*)d_in[6];
    const float* bl    = (const float*)d_in[7];
    const float* Wr    = (const float*)d_in[8];
    const float* br    = (const float*)d_in[9];
    const float* We    = (const float*)d_in[10];
    const float* att   = (const float*)d_in[11];
    const float* bconv = (const float*)d_in[12];
    const float* gamma = (const float*)d_in[13];
    const float* beta  = (const float*)d_in[14];
    const float* W1    = (const float*)d_in[15];
    const float* b1    = (const float*)d_in[16];
    const float* W2    = (const float*)d_in[17];
    const float* b2    = (const float*)d_in[18];
    float* out = (float*)d_out;

    float* bufA = nullptr;
    float* bufB = nullptr;
    cudaGetSymbolAddress((void**)&bufA, g_bufA);
    cudaGetSymbolAddress((void**)&bufB, g_bufB);

    k_init<<<256, 256>>>();
    k_deg_loop<<<(EE + 255) / 256, 256>>>(ei, ea);
    k_loopattr<<<(NN + 255) / 256, 256>>>();
    k_scan<<<1, 1024>>>();
    k_scatter<<<(EF + 255) / 256, 256>>>(ei, ea);
    k_ingemm<<<NN, HIDN>>>(x, Win, b_in);

    for (int l = 0; l < NLAY; l++) {
        const float* in  = (l % 2 == 0) ? bufA : bufB;
        float* outb      = (l % 2 == 0) ? bufB : bufA;
        const float* res = (l % 2 == 0) ? nullptr : bufA;

        k_gemm_lr<<<NN / BM, HIDN>>>(in,
                                     Wl + (size_t)l * HIDN * HIDN, bl + (size_t)l * HIDN,
                                     Wr + (size_t)l * HIDN * HIDN, br + (size_t)l * HIDN);
        k_fused<<<NN / 8, 256>>>(We + (size_t)l * EDIM * HIDN,
                                 att + (size_t)l * NHEAD * HC,
                                 bconv + (size_t)l * HIDN);
        k_bnstats<<<256, 128>>>(l);
        k_bnapply<<<2048, 256>>>(gamma + (size_t)l * HIDN, beta + (size_t)l * HIDN,
                                 res, outb, l);
    }

    k_pool<<<1024, 256>>>(batch);
    k_mlp<<<GG, 64>>>(W1, b1, W2, b2, out);
}

// round 3
// speedup vs baseline: 1.9661x; 1.3759x over previous
#include <cuda_runtime.h>

#define NN 16384
#define EE 393216
#define EF (EE + NN)      // 409600 edges incl. self loops
#define GG 256
#define HIDN 128
#define NHEAD 4
#define HC 32
#define NLAY 8
#define NDIM 21
#define EDIM 6

// ---------------- scratch (device globals; no allocation allowed) ----------
__device__ float g_bufA[NN * HIDN];
__device__ float g_bufB[NN * HIDN];
__device__ float g_xl[NN * HIDN];
__device__ float g_xr[NN * HIDN];
__device__ float g_conv[NN * HIDN];
__device__ int   g_deg[NN];
__device__ int   g_rowoff[NN + 1];
__device__ int   g_cursor[NN];
__device__ int   g_csr_src[EF];
__device__ float g_ea_csr[(size_t)EF * EDIM];
__device__ float g_stats[NLAY * 2 * HIDN];
__device__ float g_pooled[GG * HIDN];
__device__ float g_gcnt[GG];

// ---------------- init ------------------------------------------------------
__global__ void k_init() {
    int i = blockIdx.x * blockDim.x + threadIdx.x;
    int stride = gridDim.x * blockDim.x;
    for (int j = i; j < NN; j += stride) { g_deg[j] = 0; g_cursor[j] = 0; }
    for (int j = i; j < NLAY * 2 * HIDN; j += stride) g_stats[j] = 0.f;
    for (int j = i; j < GG * HIDN; j += stride) g_pooled[j] = 0.f;
    for (int j = i; j < GG; j += stride) g_gcnt[j] = 0.f;
}

// ---------------- degree count (1 atomic per edge) --------------------------
__global__ void k_deg(const int* __restrict__ ei) {
    int e = blockIdx.x * blockDim.x + threadIdx.x;
    if (e >= EE) return;
    atomicAdd(&g_deg[ei[EE + e]], 1);
}

// ---------------- exclusive scan of (deg+1): warp-shuffle version -----------
__global__ void k_scan() {
    __shared__ int wsum[32];
    int t = threadIdx.x;               // 1024 threads, 16 nodes each
    int lane = t & 31, wid = t >> 5;
    int4 d0 = ((const int4*)g_deg)[t * 4 + 0];
    int4 d1 = ((const int4*)g_deg)[t * 4 + 1];
    int4 d2 = ((const int4*)g_deg)[t * 4 + 2];
    int4 d3 = ((const int4*)g_deg)[t * 4 + 3];
    int dv[16] = {d0.x, d0.y, d0.z, d0.w, d1.x, d1.y, d1.z, d1.w,
                  d2.x, d2.y, d2.z, d2.w, d3.x, d3.y, d3.z, d3.w};
    int run = 16;
#pragma unroll
    for (int j = 0; j < 16; j++) run += dv[j];
    int v = run;
#pragma unroll
    for (int off = 1; off < 32; off <<= 1) {
        int u = __shfl_up_sync(0xffffffffu, v, off);
        if (lane >= off) v += u;
    }
    if (lane == 31) wsum[wid] = v;
    __syncthreads();
    if (wid == 0) {
        int x = wsum[lane];
#pragma unroll
        for (int off = 1; off < 32; off <<= 1) {
            int u = __shfl_up_sync(0xffffffffu, x, off);
            if (lane >= off) x += u;
        }
        wsum[lane] = x;
    }
    __syncthreads();
    int excl = v - run + (wid ? wsum[wid - 1] : 0);
    int run2 = 0;
#pragma unroll
    for (int j = 0; j < 16; j++) {
        g_rowoff[t * 16 + j] = excl + run2;
        run2 += dv[j] + 1;
    }
    if (t == 1023) g_rowoff[NN] = excl + run2;
}

// ---------------- scatter: self-loop at slot 0, real edges after ------------
__global__ void k_scatter(const int* __restrict__ ei, const float* __restrict__ ea) {
    int t = blockIdx.x * blockDim.x + threadIdx.x;
    if (t >= EF) return;
    if (t < EE) {
        int s = ei[t], d = ei[EE + t];
        int pos = g_rowoff[d] + 1 + atomicAdd(&g_cursor[d], 1);
        g_csr_src[pos] = s;
        const float* src = ea + (size_t)t * EDIM;
        float* dst = g_ea_csr + (size_t)pos * EDIM;
#pragma unroll
        for (int k = 0; k < EDIM; k++) dst[k] = src[k];
    } else {
        int n = t - EE;
        g_csr_src[g_rowoff[n]] = n;   // self loop
    }
}

// ---------------- self-loop attr = mean of incoming (from CSR) --------------
__global__ void k_loopattr() {
    int n = blockIdx.x * blockDim.x + threadIdx.x;
    if (n >= NN) return;
    int beg = g_rowoff[n], end = g_rowoff[n + 1];
    float s[EDIM];
#pragma unroll
    for (int k = 0; k < EDIM; k++) s[k] = 0.f;
    for (int j = beg + 1; j < end; j++) {
        const float* p = g_ea_csr + (size_t)j * EDIM;
#pragma unroll
        for (int k = 0; k < EDIM; k++) s[k] += p[k];
    }
    float inv = 1.0f / fmaxf((float)(end - beg - 1), 1.0f);
    float* dst = g_ea_csr + (size_t)beg * EDIM;
#pragma unroll
    for (int k = 0; k < EDIM; k++) dst[k] = s[k] * inv;
}

// ---------------- input projection: h = relu(x @ Win + b_in) ---------------
__global__ void k_ingemm(const float* __restrict__ x, const float* __restrict__ Win,
                         const float* __restrict__ b_in) {
    __shared__ float xs[NDIM];
    int n = blockIdx.x;
    int f = threadIdx.x;
    if (f < NDIM) xs[f] = x[n * NDIM + f];
    __syncthreads();
    float a = b_in[f];
#pragma unroll
    for (int k = 0; k < NDIM; k++) a += xs[k] * Win[k * HIDN + f];
    g_bufA[n * HIDN + f] = fmaxf(a, 0.f);
}

// ---------------- dual GEMM: xl = h@Wl+bl, xr = h@Wr+br --------------------
#define BM 32
__global__ void k_gemm_lr(const float* __restrict__ in,
                          const float* __restrict__ Wl, const float* __restrict__ bl,
                          const float* __restrict__ Wr, const float* __restrict__ br) {
    __shared__ float sh[BM][HIDN];
    int n0 = blockIdx.x * BM;
    int f = threadIdx.x;
#pragma unroll
    for (int m = 0; m < BM; m++) sh[m][f] = in[(n0 + m) * HIDN + f];
    __syncthreads();
    float al[BM], ar[BM];
#pragma unroll
    for (int m = 0; m < BM; m++) { al[m] = 0.f; ar[m] = 0.f; }
    for (int k = 0; k < HIDN; k++) {
        float wl = Wl[k * HIDN + f];
        float wr = Wr[k * HIDN + f];
#pragma unroll
        for (int m = 0; m < BM; m++) {
            float hv = sh[m][k];
            al[m] += hv * wl;
            ar[m] += hv * wr;
        }
    }
    float blv = bl[f], brv = br[f];
#pragma unroll
    for (int m = 0; m < BM; m++) {
        g_xl[(n0 + m) * HIDN + f] = al[m] + blv;
        g_xr[(n0 + m) * HIDN + f] = ar[m] + brv;
    }
}

// ---------------- fused score + online-softmax + aggregation ---------------
// warp per node; lane = head*8 + sub; each lane owns 4 channels of one head.
// Head score reduced with 3 shuffles inside 8-lane groups; branchless update.
__global__ void k_fused(const float* __restrict__ We_l, const float* __restrict__ att_l,
                        const float* __restrict__ bconv_l) {
    int lane = threadIdx.x & 31;
    int node = blockIdx.x * 8 + (threadIdx.x >> 5);
    int ch = ((lane >> 3) << 5) + ((lane & 7) << 2);   // head*32 + sub*4

    float4 w0 = *(const float4*)(We_l + 0 * HIDN + ch);
    float4 w1 = *(const float4*)(We_l + 1 * HIDN + ch);
    float4 w2 = *(const float4*)(We_l + 2 * HIDN + ch);
    float4 w3 = *(const float4*)(We_l + 3 * HIDN + ch);
    float4 w4 = *(const float4*)(We_l + 4 * HIDN + ch);
    float4 w5 = *(const float4*)(We_l + 5 * HIDN + ch);
    float4 at = *(const float4*)(att_l + ch);
    float4 xr4 = *(const float4*)(g_xr + (size_t)node * HIDN + ch);
    float4 bc = *(const float4*)(bconv_l + ch);

    int beg = g_rowoff[node], end = g_rowoff[node + 1];

    float m = -1e30f, den = 0.f;
    float ax = 0.f, ay = 0.f, az = 0.f, aw = 0.f;

    // software pipeline: preload edge j
    int sn = g_csr_src[beg];
    const float2* ep = (const float2*)(g_ea_csr + (size_t)beg * EDIM);
    float2 e0 = ep[0], e1 = ep[1], e2 = ep[2];
    float4 xl4 = *(const float4*)(g_xl + (size_t)sn * HIDN + ch);

    for (int j = beg; j < end; j++) {
        int sn2 = 0;
        float4 xn = xl4;
        float2 f0 = e0, f1 = e1, f2 = e2;
        if (j + 1 < end) {
            sn2 = g_csr_src[j + 1];
            const float2* ep2 = (const float2*)(g_ea_csr + (size_t)(j + 1) * EDIM);
            f0 = ep2[0]; f1 = ep2[1]; f2 = ep2[2];
            xn = *(const float4*)(g_xl + (size_t)sn2 * HIDN + ch);
        }

        float ee_x = e0.x*w0.x + e0.y*w1.x + e1.x*w2.x + e1.y*w3.x + e2.x*w4.x + e2.y*w5.x;
        float ee_y = e0.x*w0.y + e0.y*w1.y + e1.x*w2.y + e1.y*w3.y + e2.x*w4.y + e2.y*w5.y;
        float ee_z = e0.x*w0.z + e0.y*w1.z + e1.x*w2.z + e1.y*w3.z + e2.x*w4.z + e2.y*w5.z;
        float ee_w = e0.x*w0.w + e0.y*w1.w + e1.x*w2.w + e1.y*w3.w + e2.x*w4.w + e2.y*w5.w;

        float t0 = xl4.x + xr4.x + ee_x; t0 = (t0 > 0.f) ? t0 : 0.2f * t0;
        float t1 = xl4.y + xr4.y + ee_y; t1 = (t1 > 0.f) ? t1 : 0.2f * t1;
        float t2 = xl4.z + xr4.z + ee_z; t2 = (t2 > 0.f) ? t2 : 0.2f * t2;
        float t3 = xl4.w + xr4.w + ee_w; t3 = (t3 > 0.f) ? t3 : 0.2f * t3;

        float sp = t0 * at.x + t1 * at.y + t2 * at.z + t3 * at.w;
        sp += __shfl_xor_sync(0xffffffffu, sp, 1);
        sp += __shfl_xor_sync(0xffffffffu, sp, 2);
        sp += __shfl_xor_sync(0xffffffffu, sp, 4);

        // branchless online softmax
        float mn = fmaxf(m, sp);
        float r  = __expf(m - mn);
        float wg = __expf(sp - mn);
        ax = ax * r + wg * xl4.x;
        ay = ay * r + wg * xl4.y;
        az = az * r + wg * xl4.z;
        aw = aw * r + wg * xl4.w;
        den = den * r + wg;
        m = mn;

        xl4 = xn; e0 = f0; e1 = f1; e2 = f2; sn = sn2;
    }

    float inv = 1.0f / den;
    float4 o;
    o.x = ax * inv + bc.x;
    o.y = ay * inv + bc.y;
    o.z = az * inv + bc.z;
    o.w = aw * inv + bc.w;
    *(float4*)(g_conv + (size_t)node * HIDN + ch) = o;
}

// ---------------- batchnorm stats: register-accumulated ---------------------
__global__ void k_bnstats(int l) {
    int f = threadIdx.x;          // 128 threads: one feature each
    int n0 = blockIdx.x * 64;     // 256 blocks x 64 nodes
    float s = 0.f, q = 0.f;
#pragma unroll 4
    for (int n = 0; n < 64; n++) {
        float v = g_conv[(size_t)(n0 + n) * HIDN + f];
        s += v;
        q += v * v;
    }
    atomicAdd(&g_stats[l * 2 * HIDN + f], s);
    atomicAdd(&g_stats[l * 2 * HIDN + HIDN + f], q);
}

// ---------------- batchnorm apply (+ optional residual) + relu -------------
__global__ void k_bnapply(const float* __restrict__ gamma_l, const float* __restrict__ beta_l,
                          const float* __restrict__ res, float* __restrict__ out, int l) {
    int idx = blockIdx.x * blockDim.x + threadIdx.x;
    int stride = gridDim.x * blockDim.x;
    const float invN = 1.0f / (float)NN;
    for (int j = idx; j < NN * HIDN; j += stride) {
        int f = j & (HIDN - 1);
        float sum = g_stats[l * 2 * HIDN + f];
        float sq  = g_stats[l * 2 * HIDN + HIDN + f];
        float mean = sum * invN;
        float var = sq * invN - mean * mean;
        float istd = rsqrtf(var + 1e-5f);
        float y = gamma_l[f] * (g_conv[j] - mean) * istd + beta_l[f];
        if (res) y += res[j];
        out[j] = fmaxf(y, 0.f);
    }
}

// ---------------- mean pooling per graph -----------------------------------
__global__ void k_pool(const int* __restrict__ batch) {
    int idx = blockIdx.x * blockDim.x + threadIdx.x;
    int stride = gridDim.x * blockDim.x;
    for (int j = idx; j < NN * HIDN; j += stride) {
        int n = j >> 7;
        int f = j & (HIDN - 1);
        atomicAdd(&g_pooled[batch[n] * HIDN + f], g_bufA[j]);
    }
    for (int j = idx; j < NN; j += stride)
        atomicAdd(&g_gcnt[batch[j]], 1.0f);
}

// ---------------- final MLP: relu(pooled@W1+b1)@W2+b2 ----------------------
__global__ void k_mlp(const float* __restrict__ W1, const float* __restrict__ b1,
                      const float* __restrict__ W2, const float* __restrict__ b2,
                      float* __restrict__ out) {
    __shared__ float pl[HIDN];
    __shared__ float hid[64];
    int g = blockIdx.x;
    int t = threadIdx.x;
    float inv = 1.0f / fmaxf(g_gcnt[g], 1.0f);
    for (int j = t; j < HIDN; j += 64) pl[j] = g_pooled[g * HIDN + j] * inv;
    __syncthreads();
    float a = b1[t];
    for (int k = 0; k < HIDN; k++) a += pl[k] * W1[k * 64 + t];
    hid[t] = fmaxf(a, 0.f);
    __syncthreads();
    if (t < 3) {
        float lg = b2[t];
        for (int k = 0; k < 64; k++) lg += hid[k] * W2[k * 3 + t];
        out[g * 3 + t] = lg;
    }
}

// ---------------- launch ----------------------------------------------------
extern "C" void kernel_launch(void* const* d_in, const int* in_sizes, int n_in,
                              void* d_out, int out_size) {
    const float* x     = (const float*)d_in[0];
    const int*   ei    = (const int*)d_in[1];
    const float* ea    = (const float*)d_in[2];
    const int*   batch = (const int*)d_in[3];
    const float* Win   = (const float*)d_in[4];
    const float* b_in  = (const float*)d_in[5];
    const float* Wl    = (const float*)d_in[6];
    const float* bl    = (const float*)d_in[7];
    const float* Wr    = (const float*)d_in[8];
    const float* br    = (const float*)d_in[9];
    const float* We    = (const float*)d_in[10];
    const float* att   = (const float*)d_in[11];
    const float* bconv = (const float*)d_in[12];
    const float* gamma = (const float*)d_in[13];
    const float* beta  = (const float*)d_in[14];
    const float* W1    = (const float*)d_in[15];
    const float* b1    = (const float*)d_in[16];
    const float* W2    = (const float*)d_in[17];
    const float* b2    = (const float*)d_in[18];
    float* out = (float*)d_out;

    float* bufA = nullptr;
    float* bufB = nullptr;
    cudaGetSymbolAddress((void**)&bufA, g_bufA);
    cudaGetSymbolAddress((void**)&bufB, g_bufB);

    k_init<<<64, 256>>>();
    k_deg<<<(EE + 255) / 256, 256>>>(ei);
    k_scan<<<1, 1024>>>();
    k_scatter<<<(EF + 255) / 256, 256>>>(ei, ea);
    k_loopattr<<<(NN + 255) / 256, 256>>>();
    k_ingemm<<<NN, HIDN>>>(x, Win, b_in);

    for (int l = 0; l < NLAY; l++) {
        const float* in  = (l % 2 == 0) ? bufA : bufB;
        float* outb      = (l % 2 == 0) ? bufB : bufA;
        const float* res = (l % 2 == 0) ? nullptr : bufA;

        k_gemm_lr<<<NN / BM, HIDN>>>(in,
                                     Wl + (size_t)l * HIDN * HIDN, bl + (size_t)l * HIDN,
                                     Wr + (size_t)l * HIDN * HIDN, br + (size_t)l * HIDN);
        k_fused<<<NN / 8, 256>>>(We + (size_t)l * EDIM * HIDN,
                                 att + (size_t)l * NHEAD * HC,
                                 bconv + (size_t)l * HIDN);
        k_bnstats<<<256, 128>>>(l);
        k_bnapply<<<2048, 256>>>(gamma + (size_t)l * HIDN, beta + (size_t)l * HIDN,
                                 res, outb, l);
    }

    k_pool<<<1024, 256>>>(batch);
    k_mlp<<<GG, 64>>>(W1, b1, W2, b2, out);
}

// round 4
// speedup vs baseline: 2.4759x; 1.2593x over previous
#include <cuda_runtime.h>
#include <cstdint>

#define NN 16384
#define EE 393216
#define EF (EE + NN)      // 409600 edges incl. self loops
#define GG 256
#define HIDN 128
#define NHEAD 4
#define HC 32
#define NLAY 8
#define NDIM 21
#define EDIM 6

// ---------------- scratch (device globals; no allocation allowed) ----------
__device__ float g_bufA[NN * HIDN];
__device__ float g_bufB[NN * HIDN];
__device__ float g_xl[NN * HIDN];
__device__ float g_xr[NN * HIDN];
__device__ float g_conv[NN * HIDN];
__device__ int   g_deg[NN];
__device__ int   g_rowoff[NN + 1];
__device__ int   g_cursor[NN];
__device__ float g_erec[(size_t)EF * 8];   // [src_bits, ea0..ea5, pad] per edge
__device__ float g_stats[NLAY * 2 * HIDN];
__device__ float g_pooled[GG * HIDN];
__device__ float g_gcnt[GG];

// ---------------- tf32 helpers ----------------------------------------------
__device__ __forceinline__ uint32_t f2tf(float f) {
    uint32_t u;
    asm("cvt.rna.tf32.f32 %0, %1;" : "=r"(u) : "f"(f));
    return u;
}
__device__ __forceinline__ void tf_split(float f, uint32_t& hi, uint32_t& lo) {
    hi = f2tf(f);
    lo = f2tf(f - __uint_as_float(hi));
}
__device__ __forceinline__ void mma_tf32(float* d, uint32_t a0, uint32_t a1,
                                         uint32_t a2, uint32_t a3,
                                         uint32_t b0, uint32_t b1) {
    asm volatile(
        "mma.sync.aligned.m16n8k8.row.col.f32.tf32.tf32.f32 "
        "{%0,%1,%2,%3}, {%4,%5,%6,%7}, {%8,%9}, {%0,%1,%2,%3};"
        : "+f"(d[0]), "+f"(d[1]), "+f"(d[2]), "+f"(d[3])
        : "r"(a0), "r"(a1), "r"(a2), "r"(a3), "r"(b0), "r"(b1));
}

// ---------------- init ------------------------------------------------------
__global__ void k_init() {
    int i = blockIdx.x * blockDim.x + threadIdx.x;
    int stride = gridDim.x * blockDim.x;
    for (int j = i; j < NN; j += stride) { g_deg[j] = 0; g_cursor[j] = 0; }
    for (int j = i; j < NLAY * 2 * HIDN; j += stride) g_stats[j] = 0.f;
    for (int j = i; j < GG * HIDN; j += stride) g_pooled[j] = 0.f;
    for (int j = i; j < GG; j += stride) g_gcnt[j] = 0.f;
}

// ---------------- degree count ----------------------------------------------
__global__ void k_deg(const int* __restrict__ ei) {
    int e = blockIdx.x * blockDim.x + threadIdx.x;
    if (e >= EE) return;
    atomicAdd(&g_deg[ei[EE + e]], 1);
}

// ---------------- exclusive scan of (deg+1): warp-shuffle version -----------
__global__ void k_scan() {
    __shared__ int wsum[32];
    int t = threadIdx.x;               // 1024 threads, 16 nodes each
    int lane = t & 31, wid = t >> 5;
    int4 d0 = ((const int4*)g_deg)[t * 4 + 0];
    int4 d1 = ((const int4*)g_deg)[t * 4 + 1];
    int4 d2 = ((const int4*)g_deg)[t * 4 + 2];
    int4 d3 = ((const int4*)g_deg)[t * 4 + 3];
    int dv[16] = {d0.x, d0.y, d0.z, d0.w, d1.x, d1.y, d1.z, d1.w,
                  d2.x, d2.y, d2.z, d2.w, d3.x, d3.y, d3.z, d3.w};
    int run = 16;
#pragma unroll
    for (int j = 0; j < 16; j++) run += dv[j];
    int v = run;
#pragma unroll
    for (int off = 1; off < 32; off <<= 1) {
        int u = __shfl_up_sync(0xffffffffu, v, off);
        if (lane >= off) v += u;
    }
    if (lane == 31) wsum[wid] = v;
    __syncthreads();
    if (wid == 0) {
        int x = wsum[lane];
#pragma unroll
        for (int off = 1; off < 32; off <<= 1) {
            int u = __shfl_up_sync(0xffffffffu, x, off);
            if (lane >= off) x += u;
        }
        wsum[lane] = x;
    }
    __syncthreads();
    int excl = v - run + (wid ? wsum[wid - 1] : 0);
    int run2 = 0;
#pragma unroll
    for (int j = 0; j < 16; j++) {
        g_rowoff[t * 16 + j] = excl + run2;
        run2 += dv[j] + 1;
    }
    if (t == 1023) g_rowoff[NN] = excl + run2;
}

// ---------------- scatter: self-loop at slot 0, real edges after ------------
__global__ void k_scatter(const int* __restrict__ ei, const float* __restrict__ ea) {
    int t = blockIdx.x * blockDim.x + threadIdx.x;
    if (t >= EF) return;
    if (t < EE) {
        int s = ei[t], d = ei[EE + t];
        int pos = g_rowoff[d] + 1 + atomicAdd(&g_cursor[d], 1);
        const float* src = ea + (size_t)t * EDIM;
        float* dst = g_erec + (size_t)pos * 8;
        dst[0] = __int_as_float(s);
#pragma unroll
        for (int k = 0; k < EDIM; k++) dst[1 + k] = src[k];
        dst[7] = 0.f;
    } else {
        int n = t - EE;
        g_erec[(size_t)g_rowoff[n] * 8] = __int_as_float(n);   // self loop src
    }
}

// ---------------- self-loop attr = mean of incoming (from CSR records) ------
__global__ void k_loopattr() {
    int n = blockIdx.x * blockDim.x + threadIdx.x;
    if (n >= NN) return;
    int beg = g_rowoff[n], end = g_rowoff[n + 1];
    float s[EDIM];
#pragma unroll
    for (int k = 0; k < EDIM; k++) s[k] = 0.f;
    for (int j = beg + 1; j < end; j++) {
        const float* p = g_erec + (size_t)j * 8 + 1;
#pragma unroll
        for (int k = 0; k < EDIM; k++) s[k] += p[k];
    }
    float inv = 1.0f / fmaxf((float)(end - beg - 1), 1.0f);
    float* dst = g_erec + (size_t)beg * 8 + 1;
#pragma unroll
    for (int k = 0; k < EDIM; k++) dst[k] = s[k] * inv;
    g_erec[(size_t)beg * 8 + 7] = 0.f;
}

// ---------------- input projection: h = relu(x @ Win + b_in) ---------------
__global__ void k_ingemm(const float* __restrict__ x, const float* __restrict__ Win,
                         const float* __restrict__ b_in) {
    __shared__ float xs[NDIM];
    int n = blockIdx.x;
    int f = threadIdx.x;
    if (f < NDIM) xs[f] = x[n * NDIM + f];
    __syncthreads();
    float a = b_in[f];
#pragma unroll
    for (int k = 0; k < NDIM; k++) a += xs[k] * Win[k * HIDN + f];
    g_bufA[n * HIDN + f] = fmaxf(a, 0.f);
}

// ---------------- tensor-core dual GEMM (tf32 2-term split) -----------------
// grid (128, 2, 2): x = 128-row tile, y = 64-col half, z = {L, R}
// block 128 threads = 4 warps (2m x 2n), warp tile 64x32
__global__ void __launch_bounds__(128, 3)
k_gemm_mma(const float* __restrict__ H,
           const float* __restrict__ Wl, const float* __restrict__ bl,
           const float* __restrict__ Wr, const float* __restrict__ br) {
    const float* W    = blockIdx.z ? Wr : Wl;
    const float* bias = blockIdx.z ? br : bl;
    float* out        = blockIdx.z ? g_xr : g_xl;

    int lane = threadIdx.x & 31;
    int wid  = threadIdx.x >> 5;
    int mbase = blockIdx.x * 128 + (wid >> 1) * 64;
    int nbase = blockIdx.y * 64 + (wid & 1) * 32;
    int lq = lane >> 2;     // 0..7
    int lr = lane & 3;      // 0..3

    float acc[4][4][4];
#pragma unroll
    for (int mt = 0; mt < 4; mt++)
#pragma unroll
        for (int nt = 0; nt < 4; nt++)
#pragma unroll
            for (int i = 0; i < 4; i++) acc[mt][nt][i] = 0.f;

    for (int k0 = 0; k0 < HIDN; k0 += 8) {
        uint32_t ahi[4][4], alo[4][4];
#pragma unroll
        for (int mt = 0; mt < 4; mt++) {
            int r0 = mbase + mt * 16 + lq;
            int c0 = k0 + lr;
            float f0 = __ldg(&H[(size_t)r0 * HIDN + c0]);
            float f1 = __ldg(&H[(size_t)(r0 + 8) * HIDN + c0]);
            float f2 = __ldg(&H[(size_t)r0 * HIDN + c0 + 4]);
            float f3 = __ldg(&H[(size_t)(r0 + 8) * HIDN + c0 + 4]);
            tf_split(f0, ahi[mt][0], alo[mt][0]);
            tf_split(f1, ahi[mt][1], alo[mt][1]);
            tf_split(f2, ahi[mt][2], alo[mt][2]);
            tf_split(f3, ahi[mt][3], alo[mt][3]);
        }
        uint32_t bhi[4][2], blo[4][2];
#pragma unroll
        for (int nt = 0; nt < 4; nt++) {
            int kk = k0 + lr;
            int n = nbase + nt * 8 + lq;
            float g0 = __ldg(&W[(size_t)kk * HIDN + n]);
            float g1 = __ldg(&W[(size_t)(kk + 4) * HIDN + n]);
            tf_split(g0, bhi[nt][0], blo[nt][0]);
            tf_split(g1, bhi[nt][1], blo[nt][1]);
        }
#pragma unroll
        for (int mt = 0; mt < 4; mt++)
#pragma unroll
            for (int nt = 0; nt < 4; nt++) {
                mma_tf32(acc[mt][nt], ahi[mt][0], ahi[mt][1], ahi[mt][2], ahi[mt][3],
                         bhi[nt][0], bhi[nt][1]);
                mma_tf32(acc[mt][nt], ahi[mt][0], ahi[mt][1], ahi[mt][2], ahi[mt][3],
                         blo[nt][0], blo[nt][1]);
                mma_tf32(acc[mt][nt], alo[mt][0], alo[mt][1], alo[mt][2], alo[mt][3],
                         bhi[nt][0], bhi[nt][1]);
            }
    }

#pragma unroll
    for (int mt = 0; mt < 4; mt++) {
#pragma unroll
        for (int nt = 0; nt < 4; nt++) {
            int row = mbase + mt * 16 + lq;
            int col = nbase + nt * 8 + lr * 2;
            float bx = bias[col], by = bias[col + 1];
            *(float2*)&out[(size_t)row * HIDN + col] =
                make_float2(acc[mt][nt][0] + bx, acc[mt][nt][1] + by);
            *(float2*)&out[(size_t)(row + 8) * HIDN + col] =
                make_float2(acc[mt][nt][2] + bx, acc[mt][nt][3] + by);
        }
    }
}

// ---------------- fused score + online-softmax + aggregation + BN stats -----
// warp per node; lane = head*8 + sub; each lane owns 4 channels of one head.
__global__ void k_fused(const float* __restrict__ We_l, const float* __restrict__ att_l,
                        const float* __restrict__ bconv_l, int l) {
    __shared__ float s_sum[8][HIDN];
    __shared__ float s_sq[8][HIDN];
    int lane = threadIdx.x & 31;
    int wid = threadIdx.x >> 5;
    int node = blockIdx.x * 8 + wid;
    int ch = ((lane >> 3) << 5) + ((lane & 7) << 2);   // head*32 + sub*4

    float4 w0 = *(const float4*)(We_l + 0 * HIDN + ch);
    float4 w1 = *(const float4*)(We_l + 1 * HIDN + ch);
    float4 w2 = *(const float4*)(We_l + 2 * HIDN + ch);
    float4 w3 = *(const float4*)(We_l + 3 * HIDN + ch);
    float4 w4 = *(const float4*)(We_l + 4 * HIDN + ch);
    float4 w5 = *(const float4*)(We_l + 5 * HIDN + ch);
    float4 at = *(const float4*)(att_l + ch);
    float4 xr4 = *(const float4*)(g_xr + (size_t)node * HIDN + ch);
    float4 bc = *(const float4*)(bconv_l + ch);

    int beg = g_rowoff[node], end = g_rowoff[node + 1];

    float m = -1e30f, den = 0.f;
    float ax = 0.f, ay = 0.f, az = 0.f, aw = 0.f;

    const float4* rec = (const float4*)g_erec;

    // pipeline: meta prefetched 2 ahead, xl 1 ahead
    float4 A0 = rec[2 * (size_t)beg], B0 = rec[2 * (size_t)beg + 1];
    float4 xl4 = *(const float4*)(g_xl + (size_t)__float_as_int(A0.x) * HIDN + ch);
    float4 A1 = A0, B1 = B0;
    if (beg + 1 < end) { A1 = rec[2 * (size_t)(beg + 1)]; B1 = rec[2 * (size_t)(beg + 1) + 1]; }

    for (int j = beg; j < end; j++) {
        float4 xln = xl4;
        if (j + 1 < end)
            xln = *(const float4*)(g_xl + (size_t)__float_as_int(A1.x) * HIDN + ch);
        float4 A2 = A1, B2 = B1;
        if (j + 2 < end) { A2 = rec[2 * (size_t)(j + 2)]; B2 = rec[2 * (size_t)(j + 2) + 1]; }

        // ea = (A0.y, A0.z, A0.w, B0.x, B0.y, B0.z)
        float ee_x = A0.y*w0.x + A0.z*w1.x + A0.w*w2.x + B0.x*w3.x + B0.y*w4.x + B0.z*w5.x;
        float ee_y = A0.y*w0.y + A0.z*w1.y + A0.w*w2.y + B0.x*w3.y + B0.y*w4.y + B0.z*w5.y;
        float ee_z = A0.y*w0.z + A0.z*w1.z + A0.w*w2.z + B0.x*w3.z + B0.y*w4.z + B0.z*w5.z;
        float ee_w = A0.y*w0.w + A0.z*w1.w + A0.w*w2.w + B0.x*w3.w + B0.y*w4.w + B0.z*w5.w;

        float t0 = xl4.x + xr4.x + ee_x; t0 = (t0 > 0.f) ? t0 : 0.2f * t0;
        float t1 = xl4.y + xr4.y + ee_y; t1 = (t1 > 0.f) ? t1 : 0.2f * t1;
        float t2 = xl4.z + xr4.z + ee_z; t2 = (t2 > 0.f) ? t2 : 0.2f * t2;
        float t3 = xl4.w + xr4.w + ee_w; t3 = (t3 > 0.f) ? t3 : 0.2f * t3;

        float sp = t0 * at.x + t1 * at.y + t2 * at.z + t3 * at.w;
        sp += __shfl_xor_sync(0xffffffffu, sp, 1);
        sp += __shfl_xor_sync(0xffffffffu, sp, 2);
        sp += __shfl_xor_sync(0xffffffffu, sp, 4);

        float mn = fmaxf(m, sp);
        float r  = __expf(m - mn);
        float wg = __expf(sp - mn);
        ax = ax * r + wg * xl4.x;
        ay = ay * r + wg * xl4.y;
        az = az * r + wg * xl4.z;
        aw = aw * r + wg * xl4.w;
        den = den * r + wg;
        m = mn;

        xl4 = xln; A0 = A1; B0 = B1; A1 = A2; B1 = B2;
    }

    float inv = 1.0f / den;
    float4 o;
    o.x = ax * inv + bc.x;
    o.y = ay * inv + bc.y;
    o.z = az * inv + bc.z;
    o.w = aw * inv + bc.w;
    *(float4*)(g_conv + (size_t)node * HIDN + ch) = o;

    // BN stats: per-warp slabs, then block reduce + global atomics
    *(float4*)&s_sum[wid][ch] = o;
    *(float4*)&s_sq[wid][ch] = make_float4(o.x * o.x, o.y * o.y, o.z * o.z, o.w * o.w);
    __syncthreads();
    int t = threadIdx.x;
    if (t < HIDN) {
        float s = 0.f, q = 0.f;
#pragma unroll
        for (int w = 0; w < 8; w++) { s += s_sum[w][t]; q += s_sq[w][t]; }
        atomicAdd(&g_stats[l * 2 * HIDN + t], s);
        atomicAdd(&g_stats[l * 2 * HIDN + HIDN + t], q);
    }
}

// ---------------- batchnorm apply (+ optional residual) + relu -------------
__global__ void k_bnapply(const float* __restrict__ gamma_l, const float* __restrict__ beta_l,
                          const float* __restrict__ res, float* __restrict__ out, int l) {
    int idx = blockIdx.x * blockDim.x + threadIdx.x;
    int stride = gridDim.x * blockDim.x;
    const float invN = 1.0f / (float)NN;
    for (int j = idx; j < NN * HIDN; j += stride) {
        int f = j & (HIDN - 1);
        float sum = g_stats[l * 2 * HIDN + f];
        float sq  = g_stats[l * 2 * HIDN + HIDN + f];
        float mean = sum * invN;
        float var = sq * invN - mean * mean;
        float istd = rsqrtf(var + 1e-5f);
        float y = gamma_l[f] * (g_conv[j] - mean) * istd + beta_l[f];
        if (res) y += res[j];
        out[j] = fmaxf(y, 0.f);
    }
}

// ---------------- mean pooling per graph -----------------------------------
__global__ void k_pool(const int* __restrict__ batch) {
    int idx = blockIdx.x * blockDim.x + threadIdx.x;
    int stride = gridDim.x * blockDim.x;
    for (int j = idx; j < NN * HIDN; j += stride) {
        int n = j >> 7;
        int f = j & (HIDN - 1);
        atomicAdd(&g_pooled[batch[n] * HIDN + f], g_bufA[j]);
    }
    for (int j = idx; j < NN; j += stride)
        atomicAdd(&g_gcnt[batch[j]], 1.0f);
}

// ---------------- final MLP: relu(pooled@W1+b1)@W2+b2 ----------------------
__global__ void k_mlp(const float* __restrict__ W1, const float* __restrict__ b1,
                      const float* __restrict__ W2, const float* __restrict__ b2,
                      float* __restrict__ out) {
    __shared__ float pl[HIDN];
    __shared__ float hid[64];
    int g = blockIdx.x;
    int t = threadIdx.x;
    float inv = 1.0f / fmaxf(g_gcnt[g], 1.0f);
    for (int j = t; j < HIDN; j += 64) pl[j] = g_pooled[g * HIDN + j] * inv;
    __syncthreads();
    float a = b1[t];
    for (int k = 0; k < HIDN; k++) a += pl[k] * W1[k * 64 + t];
    hid[t] = fmaxf(a, 0.f);
    __syncthreads();
    if (t < 3) {
        float lg = b2[t];
        for (int k = 0; k < 64; k++) lg += hid[k] * W2[k * 3 + t];
        out[g * 3 + t] = lg;
    }
}

// ---------------- launch ----------------------------------------------------
extern "C" void kernel_launch(void* const* d_in, const int* in_sizes, int n_in,
                              void* d_out, int out_size) {
    const float* x     = (const float*)d_in[0];
    const int*   ei    = (const int*)d_in[1];
    const float* ea    = (const float*)d_in[2];
    const int*   batch = (const int*)d_in[3];
    const float* Win   = (const float*)d_in[4];
    const float* b_in  = (const float*)d_in[5];
    const float* Wl    = (const float*)d_in[6];
    const float* bl    = (const float*)d_in[7];
    const float* Wr    = (const float*)d_in[8];
    const float* br    = (const float*)d_in[9];
    const float* We    = (const float*)d_in[10];
    const float* att   = (const float*)d_in[11];
    const float* bconv = (const float*)d_in[12];
    const float* gamma = (const float*)d_in[13];
    const float* beta  = (const float*)d_in[14];
    const float* W1    = (const float*)d_in[15];
    const float* b1    = (const float*)d_in[16];
    const float* W2    = (const float*)d_in[17];
    const float* b2    = (const float*)d_in[18];
    float* out = (float*)d_out;

    float* bufA = nullptr;
    float* bufB = nullptr;
    cudaGetSymbolAddress((void**)&bufA, g_bufA);
    cudaGetSymbolAddress((void**)&bufB, g_bufB);

    k_init<<<64, 256>>>();
    k_deg<<<(EE + 255) / 256, 256>>>(ei);
    k_scan<<<1, 1024>>>();
    k_scatter<<<(EF + 255) / 256, 256>>>(ei, ea);
    k_loopattr<<<(NN + 255) / 256, 256>>>();
    k_ingemm<<<NN, HIDN>>>(x, Win, b_in);

    dim3 ggrid(NN / 128, 2, 2);
    for (int l = 0; l < NLAY; l++) {
        const float* in  = (l % 2 == 0) ? bufA : bufB;
        float* outb      = (l % 2 == 0) ? bufB : bufA;
        const float* res = (l % 2 == 0) ? nullptr : bufA;

        k_gemm_mma<<<ggrid, 128>>>(in,
                                   Wl + (size_t)l * HIDN * HIDN, bl + (size_t)l * HIDN,
                                   Wr + (size_t)l * HIDN * HIDN, br + (size_t)l * HIDN);
        k_fused<<<NN / 8, 256>>>(We + (size_t)l * EDIM * HIDN,
                                 att + (size_t)l * NHEAD * HC,
                                 bconv + (size_t)l * HIDN, l);
        k_bnapply<<<2048, 256>>>(gamma + (size_t)l * HIDN, beta + (size_t)l * HIDN,
                                 res, outb, l);
    }

    k_pool<<<1024, 256>>>(batch);
    k_mlp<<<GG, 64>>>(W1, b1, W2, b2, out);
}

// round 5
// speedup vs baseline: 2.4925x; 1.0067x over previous
#include <cuda_runtime.h>
#include <cuda_bf16.h>
#include <cstdint>

#define NN 16384
#define EE 393216
#define EF (EE + NN)      // 409600 edges incl. self loops
#define GG 256
#define HIDN 128
#define NHEAD 4
#define HC 32
#define NLAY 8
#define NDIM 21
#define EDIM 6

// ---------------- scratch (device globals; no allocation allowed) ----------
__device__ float g_bufA[NN * HIDN];
__device__ float g_bufB[NN * HIDN];
__device__ float g_xl[NN * HIDN];
__device__ float g_xr[NN * HIDN];
__device__ float g_conv[NN * HIDN];
__device__ int   g_deg[NN];
__device__ int   g_rowoff[NN + 1];
__device__ int   g_cursor[NN];
__device__ float g_erec[(size_t)EF * 8];   // [src_bits, ea0..ea5, pad] per edge
__device__ float g_stats[NLAY * 2 * HIDN];
__device__ float g_pooled[GG * HIDN];
__device__ float g_gcnt[GG];
// bf16 hi/lo split of current GEMM input h
__device__ __nv_bfloat16 g_h_hi[NN * HIDN];
__device__ __nv_bfloat16 g_h_lo[NN * HIDN];
// bf16 hi/lo split of all layer weights, transposed to [n][k]
__device__ __nv_bfloat16 g_w_hi[NLAY * 2 * HIDN * HIDN];
__device__ __nv_bfloat16 g_w_lo[NLAY * 2 * HIDN * HIDN];

// ---------------- helpers ----------------------------------------------------
__device__ __forceinline__ void bf_split(float f, __nv_bfloat16& hi, __nv_bfloat16& lo) {
    hi = __float2bfloat16(f);
    lo = __float2bfloat16(f - __bfloat162float(hi));
}
__device__ __forceinline__ void mma_bf16(float* d, uint32_t a0, uint32_t a1,
                                         uint32_t a2, uint32_t a3,
                                         uint32_t b0, uint32_t b1) {
    asm volatile(
        "mma.sync.aligned.m16n8k16.row.col.f32.bf16.bf16.f32 "
        "{%0,%1,%2,%3}, {%4,%5,%6,%7}, {%8,%9}, {%0,%1,%2,%3};"
        : "+f"(d[0]), "+f"(d[1]), "+f"(d[2]), "+f"(d[3])
        : "r"(a0), "r"(a1), "r"(a2), "r"(a3), "r"(b0), "r"(b1));
}

// ---------------- init ------------------------------------------------------
__global__ void k_init() {
    int i = blockIdx.x * blockDim.x + threadIdx.x;
    int stride = gridDim.x * blockDim.x;
    for (int j = i; j < NN; j += stride) { g_deg[j] = 0; g_cursor[j] = 0; }
    for (int j = i; j < NLAY * 2 * HIDN; j += stride) g_stats[j] = 0.f;
    for (int j = i; j < GG * HIDN; j += stride) g_pooled[j] = 0.f;
    for (int j = i; j < GG; j += stride) g_gcnt[j] = 0.f;
}

// ---------------- weight split + transpose (once per launch) ----------------
__global__ void k_wsplit(const float* __restrict__ Wl, const float* __restrict__ Wr) {
    int idx = blockIdx.x * blockDim.x + threadIdx.x;
    if (idx >= NLAY * 2 * HIDN * HIDN) return;
    int l2 = idx >> 14;
    int rem = idx & 16383;
    int n = rem >> 7;
    int k = rem & 127;
    int l = l2 >> 1, side = l2 & 1;
    const float* W = (side ? Wr : Wl) + (size_t)l * HIDN * HIDN;
    float v = W[k * HIDN + n];
    __nv_bfloat16 hi, lo;
    bf_split(v, hi, lo);
    g_w_hi[idx] = hi;
    g_w_lo[idx] = lo;
}

// ---------------- degree count ----------------------------------------------
__global__ void k_deg(const int* __restrict__ ei) {
    int e = blockIdx.x * blockDim.x + threadIdx.x;
    if (e >= EE) return;
    atomicAdd(&g_deg[ei[EE + e]], 1);
}

// ---------------- exclusive scan of (deg+1): warp-shuffle version -----------
__global__ void k_scan() {
    __shared__ int wsum[32];
    int t = threadIdx.x;               // 1024 threads, 16 nodes each
    int lane = t & 31, wid = t >> 5;
    int4 d0 = ((const int4*)g_deg)[t * 4 + 0];
    int4 d1 = ((const int4*)g_deg)[t * 4 + 1];
    int4 d2 = ((const int4*)g_deg)[t * 4 + 2];
    int4 d3 = ((const int4*)g_deg)[t * 4 + 3];
    int dv[16] = {d0.x, d0.y, d0.z, d0.w, d1.x, d1.y, d1.z, d1.w,
                  d2.x, d2.y, d2.z, d2.w, d3.x, d3.y, d3.z, d3.w};
    int run = 16;
#pragma unroll
    for (int j = 0; j < 16; j++) run += dv[j];
    int v = run;
#pragma unroll
    for (int off = 1; off < 32; off <<= 1) {
        int u = __shfl_up_sync(0xffffffffu, v, off);
        if (lane >= off) v += u;
    }
    if (lane == 31) wsum[wid] = v;
    __syncthreads();
    if (wid == 0) {
        int x = wsum[lane];
#pragma unroll
        for (int off = 1; off < 32; off <<= 1) {
            int u = __shfl_up_sync(0xffffffffu, x, off);
            if (lane >= off) x += u;
        }
        wsum[lane] = x;
    }
    __syncthreads();
    int excl = v - run + (wid ? wsum[wid - 1] : 0);
    int run2 = 0;
#pragma unroll
    for (int j = 0; j < 16; j++) {
        g_rowoff[t * 16 + j] = excl + run2;
        run2 += dv[j] + 1;
    }
    if (t == 1023) g_rowoff[NN] = excl + run2;
}

// ---------------- scatter: self-loop at slot 0, real edges after ------------
__global__ void k_scatter(const int* __restrict__ ei, const float* __restrict__ ea) {
    int t = blockIdx.x * blockDim.x + threadIdx.x;
    if (t >= EF) return;
    if (t < EE) {
        int s = ei[t], d = ei[EE + t];
        int pos = g_rowoff[d] + 1 + atomicAdd(&g_cursor[d], 1);
        const float2* src = (const float2*)(ea + (size_t)t * EDIM);  // 8B-aligned
        float2 p0 = __ldg(&src[0]), p1 = __ldg(&src[1]), p2 = __ldg(&src[2]);
        float4* dst = (float4*)(g_erec + (size_t)pos * 8);
        dst[0] = make_float4(__int_as_float(s), p0.x, p0.y, p1.x);
        dst[1] = make_float4(p1.y, p2.x, p2.y, 0.f);
    } else {
        int n = t - EE;
        g_erec[(size_t)g_rowoff[n] * 8] = __int_as_float(n);   // self loop src
    }
}

// ---------------- self-loop attr = mean of incoming (warp per node) ---------
__global__ void k_loopattr() {
    int lane = threadIdx.x & 31;
    int n = blockIdx.x * 8 + (threadIdx.x >> 5);
    if (n >= NN) return;
    int beg = g_rowoff[n], end = g_rowoff[n + 1];
    float s0 = 0.f, s1 = 0.f, s2 = 0.f, s3 = 0.f, s4 = 0.f, s5 = 0.f;
    const float4* rec = (const float4*)g_erec;
    for (int j = beg + 1 + lane; j < end; j += 32) {
        float4 A = rec[2 * (size_t)j];
        float4 B = rec[2 * (size_t)j + 1];
        s0 += A.y; s1 += A.z; s2 += A.w;
        s3 += B.x; s4 += B.y; s5 += B.z;
    }
#pragma unroll
    for (int off = 16; off > 0; off >>= 1) {
        s0 += __shfl_xor_sync(0xffffffffu, s0, off);
        s1 += __shfl_xor_sync(0xffffffffu, s1, off);
        s2 += __shfl_xor_sync(0xffffffffu, s2, off);
        s3 += __shfl_xor_sync(0xffffffffu, s3, off);
        s4 += __shfl_xor_sync(0xffffffffu, s4, off);
        s5 += __shfl_xor_sync(0xffffffffu, s5, off);
    }
    if (lane == 0) {
        float inv = 1.0f / fmaxf((float)(end - beg - 1), 1.0f);
        float4* dst = (float4*)(g_erec + (size_t)beg * 8);
        float src = g_erec[(size_t)beg * 8];
        dst[0] = make_float4(src, s0 * inv, s1 * inv, s2 * inv);
        dst[1] = make_float4(s3 * inv, s4 * inv, s5 * inv, 0.f);
    }
}

// ---------------- input projection: h = relu(x @ Win + b_in) ---------------
__global__ void k_ingemm(const float* __restrict__ x, const float* __restrict__ Win,
                         const float* __restrict__ b_in) {
    __shared__ float xs[NDIM];
    int n = blockIdx.x;
    int f = threadIdx.x;
    if (f < NDIM) xs[f] = x[n * NDIM + f];
    __syncthreads();
    float a = b_in[f];
#pragma unroll
    for (int k = 0; k < NDIM; k++) a += xs[k] * Win[k * HIDN + f];
    float v = fmaxf(a, 0.f);
    g_bufA[n * HIDN + f] = v;
    __nv_bfloat16 hi, lo;
    bf_split(v, hi, lo);
    g_h_hi[n * HIDN + f] = hi;
    g_h_lo[n * HIDN + f] = lo;
}

// ---------------- tensor-core dual GEMM (bf16 hi/lo 3-term) -----------------
// grid (128, 2, 2): x = 128-row tile, y = 64-col half, z = {L, R}
// block 128 threads = 4 warps (2m x 2n), warp tile 64x32, k-step 16
__global__ void __launch_bounds__(128)
k_gemm_bf16(const __nv_bfloat16* __restrict__ whi, const __nv_bfloat16* __restrict__ wlo,
            const float* __restrict__ bl, const float* __restrict__ br) {
    const float* bias = blockIdx.z ? br : bl;
    float* out        = blockIdx.z ? g_xr : g_xl;
    const uint32_t* Wh = (const uint32_t*)(whi + (size_t)blockIdx.z * HIDN * HIDN);
    const uint32_t* Wl_ = (const uint32_t*)(wlo + (size_t)blockIdx.z * HIDN * HIDN);
    const uint32_t* Ah = (const uint32_t*)g_h_hi;
    const uint32_t* Al = (const uint32_t*)g_h_lo;

    int lane = threadIdx.x & 31;
    int wid  = threadIdx.x >> 5;
    int mbase = blockIdx.x * 128 + (wid >> 1) * 64;
    int nbase = blockIdx.y * 64 + (wid & 1) * 32;
    int lq = lane >> 2;     // 0..7
    int lr = lane & 3;      // 0..3

    float acc[4][4][4];
#pragma unroll
    for (int mt = 0; mt < 4; mt++)
#pragma unroll
        for (int nt = 0; nt < 4; nt++)
#pragma unroll
            for (int i = 0; i < 4; i++) acc[mt][nt][i] = 0.f;

#pragma unroll
    for (int k0 = 0; k0 < HIDN; k0 += 16) {
        int k0h = k0 >> 1;  // in uint32 (bf16x2) units
        uint32_t ah[4][4], al[4][4];
#pragma unroll
        for (int mt = 0; mt < 4; mt++) {
            int r0 = mbase + mt * 16 + lq;
            int r1 = r0 + 8;
            ah[mt][0] = Ah[r0 * 64 + k0h + lr];
            ah[mt][1] = Ah[r1 * 64 + k0h + lr];
            ah[mt][2] = Ah[r0 * 64 + k0h + lr + 4];
            ah[mt][3] = Ah[r1 * 64 + k0h + lr + 4];
            al[mt][0] = Al[r0 * 64 + k0h + lr];
            al[mt][1] = Al[r1 * 64 + k0h + lr];
            al[mt][2] = Al[r0 * 64 + k0h + lr + 4];
            al[mt][3] = Al[r1 * 64 + k0h + lr + 4];
        }
        uint32_t bh[4][2], blr[4][2];
#pragma unroll
        for (int nt = 0; nt < 4; nt++) {
            int n = nbase + nt * 8 + lq;
            bh[nt][0]  = Wh[n * 64 + k0h + lr];
            bh[nt][1]  = Wh[n * 64 + k0h + lr + 4];
            blr[nt][0] = Wl_[n * 64 + k0h + lr];
            blr[nt][1] = Wl_[n * 64 + k0h + lr + 4];
        }
#pragma unroll
        for (int mt = 0; mt < 4; mt++)
#pragma unroll
            for (int nt = 0; nt < 4; nt++) {
                mma_bf16(acc[mt][nt], ah[mt][0], ah[mt][1], ah[mt][2], ah[mt][3],
                         bh[nt][0], bh[nt][1]);
                mma_bf16(acc[mt][nt], ah[mt][0], ah[mt][1], ah[mt][2], ah[mt][3],
                         blr[nt][0], blr[nt][1]);
                mma_bf16(acc[mt][nt], al[mt][0], al[mt][1], al[mt][2], al[mt][3],
                         bh[nt][0], bh[nt][1]);
            }
    }

#pragma unroll
    for (int mt = 0; mt < 4; mt++) {
#pragma unroll
        for (int nt = 0; nt < 4; nt++) {
            int row = mbase + mt * 16 + lq;
            int col = nbase + nt * 8 + lr * 2;
            float bx = bias[col], by = bias[col + 1];
            *(float2*)&out[(size_t)row * HIDN + col] =
                make_float2(acc[mt][nt][0] + bx, acc[mt][nt][1] + by);
            *(float2*)&out[(size_t)(row + 8) * HIDN + col] =
                make_float2(acc[mt][nt][2] + bx, acc[mt][nt][3] + by);
        }
    }
}

// ---------------- fused score + online-softmax + aggregation + BN stats -----
// warp per node; lane = head*8 + sub; each lane owns 4 channels of one head.
__global__ void k_fused(const float* __restrict__ We_l, const float* __restrict__ att_l,
                        const float* __restrict__ bconv_l, int l) {
    __shared__ float s_sum[8][HIDN];
    __shared__ float s_sq[8][HIDN];
    int lane = threadIdx.x & 31;
    int wid = threadIdx.x >> 5;
    int node = blockIdx.x * 8 + wid;
    int ch = ((lane >> 3) << 5) + ((lane & 7) << 2);   // head*32 + sub*4

    float4 w0 = *(const float4*)(We_l + 0 * HIDN + ch);
    float4 w1 = *(const float4*)(We_l + 1 * HIDN + ch);
    float4 w2 = *(const float4*)(We_l + 2 * HIDN + ch);
    float4 w3 = *(const float4*)(We_l + 3 * HIDN + ch);
    float4 w4 = *(const float4*)(We_l + 4 * HIDN + ch);
    float4 w5 = *(const float4*)(We_l + 5 * HIDN + ch);
    float4 at = *(const float4*)(att_l + ch);
    float4 xr4 = *(const float4*)(g_xr + (size_t)node * HIDN + ch);
    float4 bc = *(const float4*)(bconv_l + ch);

    int beg = g_rowoff[node], end = g_rowoff[node + 1];

    float m = -1e30f, den = 0.f;
    float ax = 0.f, ay = 0.f, az = 0.f, aw = 0.f;

    const float4* rec = (const float4*)g_erec;

    // pipeline: meta prefetched 2 ahead, xl 1 ahead
    float4 A0 = rec[2 * (size_t)beg], B0 = rec[2 * (size_t)beg + 1];
    float4 xl4 = *(const float4*)(g_xl + (size_t)__float_as_int(A0.x) * HIDN + ch);
    float4 A1 = A0, B1 = B0;
    if (beg + 1 < end) { A1 = rec[2 * (size_t)(beg + 1)]; B1 = rec[2 * (size_t)(beg + 1) + 1]; }

    for (int j = beg; j < end; j++) {
        float4 xln = xl4;
        if (j + 1 < end)
            xln = *(const float4*)(g_xl + (size_t)__float_as_int(A1.x) * HIDN + ch);
        float4 A2 = A1, B2 = B1;
        if (j + 2 < end) { A2 = rec[2 * (size_t)(j + 2)]; B2 = rec[2 * (size_t)(j + 2) + 1]; }

        // ea = (A0.y, A0.z, A0.w, B0.x, B0.y, B0.z)
        float ee_x = A0.y*w0.x + A0.z*w1.x + A0.w*w2.x + B0.x*w3.x + B0.y*w4.x + B0.z*w5.x;
        float ee_y = A0.y*w0.y + A0.z*w1.y + A0.w*w2.y + B0.x*w3.y + B0.y*w4.y + B0.z*w5.y;
        float ee_z = A0.y*w0.z + A0.z*w1.z + A0.w*w2.z + B0.x*w3.z + B0.y*w4.z + B0.z*w5.z;
        float ee_w = A0.y*w0.w + A0.z*w1.w + A0.w*w2.w + B0.x*w3.w + B0.y*w4.w + B0.z*w5.w;

        float t0 = xl4.x + xr4.x + ee_x; t0 = (t0 > 0.f) ? t0 : 0.2f * t0;
        float t1 = xl4.y + xr4.y + ee_y; t1 = (t1 > 0.f) ? t1 : 0.2f * t1;
        float t2 = xl4.z + xr4.z + ee_z; t2 = (t2 > 0.f) ? t2 : 0.2f * t2;
        float t3 = xl4.w + xr4.w + ee_w; t3 = (t3 > 0.f) ? t3 : 0.2f * t3;

        float sp = t0 * at.x + t1 * at.y + t2 * at.z + t3 * at.w;
        sp += __shfl_xor_sync(0xffffffffu, sp, 1);
        sp += __shfl_xor_sync(0xffffffffu, sp, 2);
        sp += __shfl_xor_sync(0xffffffffu, sp, 4);

        float mn = fmaxf(m, sp);
        float r  = __expf(m - mn);
        float wg = __expf(sp - mn);
        ax = ax * r + wg * xl4.x;
        ay = ay * r + wg * xl4.y;
        az = az * r + wg * xl4.z;
        aw = aw * r + wg * xl4.w;
        den = den * r + wg;
        m = mn;

        xl4 = xln; A0 = A1; B0 = B1; A1 = A2; B1 = B2;
    }

    float inv = 1.0f / den;
    float4 o;
    o.x = ax * inv + bc.x;
    o.y = ay * inv + bc.y;
    o.z = az * inv + bc.z;
    o.w = aw * inv + bc.w;
    *(float4*)(g_conv + (size_t)node * HIDN + ch) = o;

    // BN stats: per-warp slabs, then block reduce + global atomics
    *(float4*)&s_sum[wid][ch] = o;
    *(float4*)&s_sq[wid][ch] = make_float4(o.x * o.x, o.y * o.y, o.z * o.z, o.w * o.w);
    __syncthreads();
    int t = threadIdx.x;
    if (t < HIDN) {
        float s = 0.f, q = 0.f;
#pragma unroll
        for (int w = 0; w < 8; w++) { s += s_sum[w][t]; q += s_sq[w][t]; }
        atomicAdd(&g_stats[l * 2 * HIDN + t], s);
        atomicAdd(&g_stats[l * 2 * HIDN + HIDN + t], q);
    }
}

// ---------------- batchnorm apply (+ residual) + relu + bf16 split ----------
__global__ void k_bnapply(const float* __restrict__ gamma_l, const float* __restrict__ beta_l,
                          const float* __restrict__ res, float* __restrict__ out, int l) {
    int j4 = blockIdx.x * blockDim.x + threadIdx.x;   // one float4 per thread
    if (j4 >= NN * HIDN / 4) return;
    int f4 = (j4 & 31);                                // float4-index within feature dim
    const float invN = 1.0f / (float)NN;

    float4 sum4 = ((const float4*)(g_stats + l * 2 * HIDN))[f4];
    float4 sq4  = ((const float4*)(g_stats + l * 2 * HIDN + HIDN))[f4];
    float4 gm = ((const float4*)gamma_l)[f4];
    float4 bt = ((const float4*)beta_l)[f4];
    float4 c = ((const float4*)g_conv)[j4];

    float4 y;
    {
        float mean = sum4.x * invN, var = sq4.x * invN - mean * mean;
        y.x = gm.x * (c.x - mean) * rsqrtf(var + 1e-5f) + bt.x;
        mean = sum4.y * invN; var = sq4.y * invN - mean * mean;
        y.y = gm.y * (c.y - mean) * rsqrtf(var + 1e-5f) + bt.y;
        mean = sum4.z * invN; var = sq4.z * invN - mean * mean;
        y.z = gm.z * (c.z - mean) * rsqrtf(var + 1e-5f) + bt.z;
        mean = sum4.w * invN; var = sq4.w * invN - mean * mean;
        y.w = gm.w * (c.w - mean) * rsqrtf(var + 1e-5f) + bt.w;
    }
    if (res) {
        float4 r4 = ((const float4*)res)[j4];
        y.x += r4.x; y.y += r4.y; y.z += r4.z; y.w += r4.w;
    }
    y.x = fmaxf(y.x, 0.f); y.y = fmaxf(y.y, 0.f);
    y.z = fmaxf(y.z, 0.f); y.w = fmaxf(y.w, 0.f);
    ((float4*)out)[j4] = y;

    __nv_bfloat16 h0, l0, h1, l1, h2, l2, h3, l3;
    bf_split(y.x, h0, l0); bf_split(y.y, h1, l1);
    bf_split(y.z, h2, l2); bf_split(y.w, h3, l3);
    ((__nv_bfloat162*)g_h_hi)[j4 * 2]     = __nv_bfloat162(h0, h1);
    ((__nv_bfloat162*)g_h_hi)[j4 * 2 + 1] = __nv_bfloat162(h2, h3);
    ((__nv_bfloat162*)g_h_lo)[j4 * 2]     = __nv_bfloat162(l0, l1);
    ((__nv_bfloat162*)g_h_lo)[j4 * 2 + 1] = __nv_bfloat162(l2, l3);
}

// ---------------- mean pooling per graph -----------------------------------
__global__ void k_pool(const int* __restrict__ batch) {
    int idx = blockIdx.x * blockDim.x + threadIdx.x;
    int stride = gridDim.x * blockDim.x;
    for (int j = idx; j < NN * HIDN; j += stride) {
        int n = j >> 7;
        int f = j & (HIDN - 1);
        atomicAdd(&g_pooled[batch[n] * HIDN + f], g_bufA[j]);
    }
    for (int j = idx; j < NN; j += stride)
        atomicAdd(&g_gcnt[batch[j]], 1.0f);
}

// ---------------- final MLP: relu(pooled@W1+b1)@W2+b2 ----------------------
__global__ void k_mlp(const float* __restrict__ W1, const float* __restrict__ b1,
                      const float* __restrict__ W2, const float* __restrict__ b2,
                      float* __restrict__ out) {
    __shared__ float pl[HIDN];
    __shared__ float hid[64];
    int g = blockIdx.x;
    int t = threadIdx.x;
    float inv = 1.0f / fmaxf(g_gcnt[g], 1.0f);
    for (int j = t; j < HIDN; j += 64) pl[j] = g_pooled[g * HIDN + j] * inv;
    __syncthreads();
    float a = b1[t];
    for (int k = 0; k < HIDN; k++) a += pl[k] * W1[k * 64 + t];
    hid[t] = fmaxf(a, 0.f);
    __syncthreads();
    if (t < 3) {
        float lg = b2[t];
        for (int k = 0; k < 64; k++) lg += hid[k] * W2[k * 3 + t];
        out[g * 3 + t] = lg;
    }
}

// ---------------- launch ----------------------------------------------------
extern "C" void kernel_launch(void* const* d_in, const int* in_sizes, int n_in,
                              void* d_out, int out_size) {
    const float* x     = (const float*)d_in[0];
    const int*   ei    = (const int*)d_in[1];
    const float* ea    = (const float*)d_in[2];
    const int*   batch = (const int*)d_in[3];
    const float* Win   = (const float*)d_in[4];
    const float* b_in  = (const float*)d_in[5];
    const float* Wl    = (const float*)d_in[6];
    const float* bl    = (const float*)d_in[7];
    const float* Wr    = (const float*)d_in[8];
    const float* br    = (const float*)d_in[9];
    const float* We    = (const float*)d_in[10];
    const float* att   = (const float*)d_in[11];
    const float* bconv = (const float*)d_in[12];
    const float* gamma = (const float*)d_in[13];
    const float* beta  = (const float*)d_in[14];
    const float* W1    = (const float*)d_in[15];
    const float* b1    = (const float*)d_in[16];
    const float* W2    = (const float*)d_in[17];
    const float* b2    = (const float*)d_in[18];
    float* out = (float*)d_out;

    float* bufA = nullptr;
    float* bufB = nullptr;
    cudaGetSymbolAddress((void**)&bufA, g_bufA);
    cudaGetSymbolAddress((void**)&bufB, g_bufB);
    __nv_bfloat16* whi = nullptr;
    __nv_bfloat16* wlo = nullptr;
    cudaGetSymbolAddress((void**)&whi, g_w_hi);
    cudaGetSymbolAddress((void**)&wlo, g_w_lo);

    k_init<<<64, 256>>>();
    k_wsplit<<<(NLAY * 2 * HIDN * HIDN + 255) / 256, 256>>>(Wl, Wr);
    k_deg<<<(EE + 255) / 256, 256>>>(ei);
    k_scan<<<1, 1024>>>();
    k_scatter<<<(EF + 255) / 256, 256>>>(ei, ea);
    k_loopattr<<<NN / 8, 256>>>();
    k_ingemm<<<NN, HIDN>>>(x, Win, b_in);

    dim3 ggrid(NN / 128, 2, 2);
    for (int l = 0; l < NLAY; l++) {
        float* outb      = (l % 2 == 0) ? bufB : bufA;
        const float* res = (l % 2 == 0) ? nullptr : bufA;

        k_gemm_bf16<<<ggrid, 128>>>(whi + (size_t)l * 2 * HIDN * HIDN,
                                    wlo + (size_t)l * 2 * HIDN * HIDN,
                                    bl + (size_t)l * HIDN, br + (size_t)l * HIDN);
        k_fused<<<NN / 8, 256>>>(We + (size_t)l * EDIM * HIDN,
                                 att + (size_t)l * NHEAD * HC,
                                 bconv + (size_t)l * HIDN, l);
        k_bnapply<<<NN * HIDN / 4 / 256, 256>>>(gamma + (size_t)l * HIDN,
                                                beta + (size_t)l * HIDN,
                                                res, outb, l);
    }

    k_pool<<<1024, 256>>>(batch);
    k_mlp<<<GG, 64>>>(W1, b1, W2, b2, out);
}

// round 6
// speedup vs baseline: 2.9344x; 1.1773x over previous
#include <cuda_runtime.h>
#include <cuda_bf16.h>
#include <cstdint>

#define NN 16384
#define EE 393216
#define EF (EE + NN)      // 409600 edges incl. self loops
#define GG 256
#define HIDN 128
#define NHEAD 4
#define HC 32
#define NLAY 8
#define NDIM 21
#define EDIM 6

// ---------------- scratch (device globals; no allocation allowed) ----------
__device__ float g_bufA[NN * HIDN];
__device__ float g_bufB[NN * HIDN];
__device__ float g_xl[NN * HIDN];
__device__ float g_xr[NN * HIDN];
__device__ float g_conv[NN * HIDN];
__device__ int   g_deg[NN];
__device__ int   g_rowoff[NN + 1];
__device__ int   g_cursor[NN];
__device__ float g_erec[(size_t)EF * 8];   // [src_bits, ea0..ea5, pad] per edge
__device__ float g_stats[NLAY * 2 * HIDN];
__device__ float g_pooled[GG * HIDN];
__device__ float g_gcnt[GG];
__device__ __nv_bfloat16 g_h_hi[NN * HIDN];
__device__ __nv_bfloat16 g_h_lo[NN * HIDN];
__device__ __nv_bfloat16 g_w_hi[NLAY * 2 * HIDN * HIDN];
__device__ __nv_bfloat16 g_w_lo[NLAY * 2 * HIDN * HIDN];

// ---------------- helpers ----------------------------------------------------
__device__ __forceinline__ void bf_split(float f, __nv_bfloat16& hi, __nv_bfloat16& lo) {
    hi = __float2bfloat16(f);
    lo = __float2bfloat16(f - __bfloat162float(hi));
}
__device__ __forceinline__ void mma_bf16(float* d, uint32_t a0, uint32_t a1,
                                         uint32_t a2, uint32_t a3,
                                         uint32_t b0, uint32_t b1) {
    asm volatile(
        "mma.sync.aligned.m16n8k16.row.col.f32.bf16.bf16.f32 "
        "{%0,%1,%2,%3}, {%4,%5,%6,%7}, {%8,%9}, {%0,%1,%2,%3};"
        : "+f"(d[0]), "+f"(d[1]), "+f"(d[2]), "+f"(d[3])
        : "r"(a0), "r"(a1), "r"(a2), "r"(a3), "r"(b0), "r"(b1));
}

// ---------------- init ------------------------------------------------------
__global__ void k_init() {
    int i = blockIdx.x * blockDim.x + threadIdx.x;
    int stride = gridDim.x * blockDim.x;
    for (int j = i; j < NN; j += stride) { g_deg[j] = 0; g_cursor[j] = 0; }
    for (int j = i; j < NLAY * 2 * HIDN; j += stride) g_stats[j] = 0.f;
    for (int j = i; j < GG * HIDN; j += stride) g_pooled[j] = 0.f;
    for (int j = i; j < GG; j += stride) g_gcnt[j] = 0.f;
}

// ---------------- weight split + transpose (once per launch) ----------------
__global__ void k_wsplit(const float* __restrict__ Wl, const float* __restrict__ Wr) {
    int idx = blockIdx.x * blockDim.x + threadIdx.x;
    if (idx >= NLAY * 2 * HIDN * HIDN) return;
    int l2 = idx >> 14;
    int rem = idx & 16383;
    int n = rem >> 7;
    int k = rem & 127;
    int l = l2 >> 1, side = l2 & 1;
    const float* W = (side ? Wr : Wl) + (size_t)l * HIDN * HIDN;
    float v = W[k * HIDN + n];
    __nv_bfloat16 hi, lo;
    bf_split(v, hi, lo);
    g_w_hi[idx] = hi;
    g_w_lo[idx] = lo;
}

// ---------------- degree count ----------------------------------------------
__global__ void k_deg(const int* __restrict__ ei) {
    int e = blockIdx.x * blockDim.x + threadIdx.x;
    if (e >= EE) return;
    atomicAdd(&g_deg[ei[EE + e]], 1);
}

// ---------------- exclusive scan of (deg+1): warp-shuffle version -----------
__global__ void k_scan() {
    __shared__ int wsum[32];
    int t = threadIdx.x;               // 1024 threads, 16 nodes each
    int lane = t & 31, wid = t >> 5;
    int4 d0 = ((const int4*)g_deg)[t * 4 + 0];
    int4 d1 = ((const int4*)g_deg)[t * 4 + 1];
    int4 d2 = ((const int4*)g_deg)[t * 4 + 2];
    int4 d3 = ((const int4*)g_deg)[t * 4 + 3];
    int dv[16] = {d0.x, d0.y, d0.z, d0.w, d1.x, d1.y, d1.z, d1.w,
                  d2.x, d2.y, d2.z, d2.w, d3.x, d3.y, d3.z, d3.w};
    int run = 16;
#pragma unroll
    for (int j = 0; j < 16; j++) run += dv[j];
    int v = run;
#pragma unroll
    for (int off = 1; off < 32; off <<= 1) {
        int u = __shfl_up_sync(0xffffffffu, v, off);
        if (lane >= off) v += u;
    }
    if (lane == 31) wsum[wid] = v;
    __syncthreads();
    if (wid == 0) {
        int x = wsum[lane];
#pragma unroll
        for (int off = 1; off < 32; off <<= 1) {
            int u = __shfl_up_sync(0xffffffffu, x, off);
            if (lane >= off) x += u;
        }
        wsum[lane] = x;
    }
    __syncthreads();
    int excl = v - run + (wid ? wsum[wid - 1] : 0);
    int run2 = 0;
#pragma unroll
    for (int j = 0; j < 16; j++) {
        g_rowoff[t * 16 + j] = excl + run2;
        run2 += dv[j] + 1;
    }
    if (t == 1023) g_rowoff[NN] = excl + run2;
}

// ---------------- scatter: self-loop at slot 0, real edges after ------------
__global__ void k_scatter(const int* __restrict__ ei, const float* __restrict__ ea) {
    int t = blockIdx.x * blockDim.x + threadIdx.x;
    if (t >= EF) return;
    if (t < EE) {
        int s = ei[t], d = ei[EE + t];
        int pos = g_rowoff[d] + 1 + atomicAdd(&g_cursor[d], 1);
        const float2* src = (const float2*)(ea + (size_t)t * EDIM);  // 8B-aligned
        float2 p0 = __ldg(&src[0]), p1 = __ldg(&src[1]), p2 = __ldg(&src[2]);
        float4* dst = (float4*)(g_erec + (size_t)pos * 8);
        dst[0] = make_float4(__int_as_float(s), p0.x, p0.y, p1.x);
        dst[1] = make_float4(p1.y, p2.x, p2.y, 0.f);
    } else {
        int n = t - EE;
        g_erec[(size_t)g_rowoff[n] * 8] = __int_as_float(n);   // self loop src
    }
}

// ---------------- self-loop attr = mean of incoming (warp per node) ---------
__global__ void k_loopattr() {
    int lane = threadIdx.x & 31;
    int n = blockIdx.x * 8 + (threadIdx.x >> 5);
    if (n >= NN) return;
    int beg = g_rowoff[n], end = g_rowoff[n + 1];
    float s0 = 0.f, s1 = 0.f, s2 = 0.f, s3 = 0.f, s4 = 0.f, s5 = 0.f;
    const float4* rec = (const float4*)g_erec;
    for (int j = beg + 1 + lane; j < end; j += 32) {
        float4 A = rec[2 * (size_t)j];
        float4 B = rec[2 * (size_t)j + 1];
        s0 += A.y; s1 += A.z; s2 += A.w;
        s3 += B.x; s4 += B.y; s5 += B.z;
    }
#pragma unroll
    for (int off = 16; off > 0; off >>= 1) {
        s0 += __shfl_xor_sync(0xffffffffu, s0, off);
        s1 += __shfl_xor_sync(0xffffffffu, s1, off);
        s2 += __shfl_xor_sync(0xffffffffu, s2, off);
        s3 += __shfl_xor_sync(0xffffffffu, s3, off);
        s4 += __shfl_xor_sync(0xffffffffu, s4, off);
        s5 += __shfl_xor_sync(0xffffffffu, s5, off);
    }
    if (lane == 0) {
        float inv = 1.0f / fmaxf((float)(end - beg - 1), 1.0f);
        float4* dst = (float4*)(g_erec + (size_t)beg * 8);
        float src = g_erec[(size_t)beg * 8];
        dst[0] = make_float4(src, s0 * inv, s1 * inv, s2 * inv);
        dst[1] = make_float4(s3 * inv, s4 * inv, s5 * inv, 0.f);
    }
}

// ---------------- input projection: h = relu(x @ Win + b_in) ---------------
__global__ void k_ingemm(const float* __restrict__ x, const float* __restrict__ Win,
                         const float* __restrict__ b_in) {
    __shared__ float xs[NDIM];
    int n = blockIdx.x;
    int f = threadIdx.x;
    if (f < NDIM) xs[f] = x[n * NDIM + f];
    __syncthreads();
    float a = b_in[f];
#pragma unroll
    for (int k = 0; k < NDIM; k++) a += xs[k] * Win[k * HIDN + f];
    float v = fmaxf(a, 0.f);
    g_bufA[n * HIDN + f] = v;
    __nv_bfloat16 hi, lo;
    bf_split(v, hi, lo);
    g_h_hi[n * HIDN + f] = hi;
    g_h_lo[n * HIDN + f] = lo;
}

// ---------------- tensor-core dual GEMM (bf16 hi/lo 3-term) -----------------
__global__ void __launch_bounds__(128)
k_gemm_bf16(const __nv_bfloat16* __restrict__ whi, const __nv_bfloat16* __restrict__ wlo,
            const float* __restrict__ bl, const float* __restrict__ br) {
    const float* bias = blockIdx.z ? br : bl;
    float* out        = blockIdx.z ? g_xr : g_xl;
    const uint32_t* Wh = (const uint32_t*)(whi + (size_t)blockIdx.z * HIDN * HIDN);
    const uint32_t* Wl_ = (const uint32_t*)(wlo + (size_t)blockIdx.z * HIDN * HIDN);
    const uint32_t* Ah = (const uint32_t*)g_h_hi;
    const uint32_t* Al = (const uint32_t*)g_h_lo;

    int lane = threadIdx.x & 31;
    int wid  = threadIdx.x >> 5;
    int mbase = blockIdx.x * 128 + (wid >> 1) * 64;
    int nbase = blockIdx.y * 64 + (wid & 1) * 32;
    int lq = lane >> 2;     // 0..7
    int lr = lane & 3;      // 0..3

    float acc[4][4][4];
#pragma unroll
    for (int mt = 0; mt < 4; mt++)
#pragma unroll
        for (int nt = 0; nt < 4; nt++)
#pragma unroll
            for (int i = 0; i < 4; i++) acc[mt][nt][i] = 0.f;

#pragma unroll
    for (int k0 = 0; k0 < HIDN; k0 += 16) {
        int k0h = k0 >> 1;  // in uint32 (bf16x2) units
        uint32_t ah[4][4], al[4][4];
#pragma unroll
        for (int mt = 0; mt < 4; mt++) {
            int r0 = mbase + mt * 16 + lq;
            int r1 = r0 + 8;
            ah[mt][0] = Ah[r0 * 64 + k0h + lr];
            ah[mt][1] = Ah[r1 * 64 + k0h + lr];
            ah[mt][2] = Ah[r0 * 64 + k0h + lr + 4];
            ah[mt][3] = Ah[r1 * 64 + k0h + lr + 4];
            al[mt][0] = Al[r0 * 64 + k0h + lr];
            al[mt][1] = Al[r1 * 64 + k0h + lr];
            al[mt][2] = Al[r0 * 64 + k0h + lr + 4];
            al[mt][3] = Al[r1 * 64 + k0h + lr + 4];
        }
        uint32_t bh[4][2], blr[4][2];
#pragma unroll
        for (int nt = 0; nt < 4; nt++) {
            int n = nbase + nt * 8 + lq;
            bh[nt][0]  = Wh[n * 64 + k0h + lr];
            bh[nt][1]  = Wh[n * 64 + k0h + lr + 4];
            blr[nt][0] = Wl_[n * 64 + k0h + lr];
            blr[nt][1] = Wl_[n * 64 + k0h + lr + 4];
        }
#pragma unroll
        for (int mt = 0; mt < 4; mt++)
#pragma unroll
            for (int nt = 0; nt < 4; nt++) {
                mma_bf16(acc[mt][nt], ah[mt][0], ah[mt][1], ah[mt][2], ah[mt][3],
                         bh[nt][0], bh[nt][1]);
                mma_bf16(acc[mt][nt], ah[mt][0], ah[mt][1], ah[mt][2], ah[mt][3],
                         blr[nt][0], blr[nt][1]);
                mma_bf16(acc[mt][nt], al[mt][0], al[mt][1], al[mt][2], al[mt][3],
                         bh[nt][0], bh[nt][1]);
            }
    }

#pragma unroll
    for (int mt = 0; mt < 4; mt++) {
#pragma unroll
        for (int nt = 0; nt < 4; nt++) {
            int row = mbase + mt * 16 + lq;
            int col = nbase + nt * 8 + lr * 2;
            float bx = bias[col], by = bias[col + 1];
            *(float2*)&out[(size_t)row * HIDN + col] =
                make_float2(acc[mt][nt][0] + bx, acc[mt][nt][1] + by);
            *(float2*)&out[(size_t)(row + 8) * HIDN + col] =
                make_float2(acc[mt][nt][2] + bx, acc[mt][nt][3] + by);
        }
    }
}

// ---------------- fused score + online-softmax + aggregation + BN stats -----
// warp per node; lane = head*8 + sub; 4-edge batched to break dep chains.
__global__ void k_fused(const float* __restrict__ We_l, const float* __restrict__ att_l,
                        const float* __restrict__ bconv_l, int l) {
    __shared__ float s_sum[8][HIDN];
    __shared__ float s_sq[8][HIDN];
    int lane = threadIdx.x & 31;
    int wid = threadIdx.x >> 5;
    int node = blockIdx.x * 8 + wid;
    int ch = ((lane >> 3) << 5) + ((lane & 7) << 2);   // head*32 + sub*4

    float4 w0 = *(const float4*)(We_l + 0 * HIDN + ch);
    float4 w1 = *(const float4*)(We_l + 1 * HIDN + ch);
    float4 w2 = *(const float4*)(We_l + 2 * HIDN + ch);
    float4 w3 = *(const float4*)(We_l + 3 * HIDN + ch);
    float4 w4 = *(const float4*)(We_l + 4 * HIDN + ch);
    float4 w5 = *(const float4*)(We_l + 5 * HIDN + ch);
    float4 at = *(const float4*)(att_l + ch);
    float4 xr4 = *(const float4*)(g_xr + (size_t)node * HIDN + ch);
    float4 bc = *(const float4*)(bconv_l + ch);

    int beg = g_rowoff[node], end = g_rowoff[node + 1];

    float m = -1e30f, den = 0.f;
    float ax = 0.f, ay = 0.f, az = 0.f, aw = 0.f;

    const float4* rec = (const float4*)g_erec;

    // score for one edge given its record halves and xl row
    auto edge_score = [&](const float4& A, const float4& B, const float4& X) -> float {
        float ee_x = A.y*w0.x + A.z*w1.x + A.w*w2.x + B.x*w3.x + B.y*w4.x + B.z*w5.x;
        float ee_y = A.y*w0.y + A.z*w1.y + A.w*w2.y + B.x*w3.y + B.y*w4.y + B.z*w5.y;
        float ee_z = A.y*w0.z + A.z*w1.z + A.w*w2.z + B.x*w3.z + B.y*w4.z + B.z*w5.z;
        float ee_w = A.y*w0.w + A.z*w1.w + A.w*w2.w + B.x*w3.w + B.y*w4.w + B.z*w5.w;
        float t0 = X.x + xr4.x + ee_x; t0 = (t0 > 0.f) ? t0 : 0.2f * t0;
        float t1 = X.y + xr4.y + ee_y; t1 = (t1 > 0.f) ? t1 : 0.2f * t1;
        float t2 = X.z + xr4.z + ee_z; t2 = (t2 > 0.f) ? t2 : 0.2f * t2;
        float t3 = X.w + xr4.w + ee_w; t3 = (t3 > 0.f) ? t3 : 0.2f * t3;
        return t0 * at.x + t1 * at.y + t2 * at.z + t3 * at.w;
    };

    int j = beg;
    int nfull = (end - beg) & ~3;
    int gend = beg + nfull;

    if (j < gend) {
        float4 A[4], Bv[4];
#pragma unroll
        for (int u = 0; u < 4; u++) {
            A[u]  = rec[2 * (size_t)(j + u)];
            Bv[u] = rec[2 * (size_t)(j + u) + 1];
        }
        for (; j < gend; j += 4) {
            // gather xl rows for this group (4 independent LDG.128)
            float4 X[4];
#pragma unroll
            for (int u = 0; u < 4; u++)
                X[u] = *(const float4*)(g_xl + (size_t)__float_as_int(A[u].x) * HIDN + ch);

            // prefetch next group's records
            float4 An[4], Bn[4];
            if (j + 8 <= gend) {
#pragma unroll
                for (int u = 0; u < 4; u++) {
                    An[u] = rec[2 * (size_t)(j + 4 + u)];
                    Bn[u] = rec[2 * (size_t)(j + 4 + u) + 1];
                }
            }

            // 4 independent scores; shuffle trees interleave
            float sp0 = edge_score(A[0], Bv[0], X[0]);
            float sp1 = edge_score(A[1], Bv[1], X[1]);
            float sp2 = edge_score(A[2], Bv[2], X[2]);
            float sp3 = edge_score(A[3], Bv[3], X[3]);
#pragma unroll
            for (int off = 1; off <= 4; off <<= 1) {
                sp0 += __shfl_xor_sync(0xffffffffu, sp0, off);
                sp1 += __shfl_xor_sync(0xffffffffu, sp1, off);
                sp2 += __shfl_xor_sync(0xffffffffu, sp2, off);
                sp3 += __shfl_xor_sync(0xffffffffu, sp3, off);
            }

            // joint softmax update (one rescale per group)
            float gm = fmaxf(fmaxf(sp0, sp1), fmaxf(sp2, sp3));
            float mn = fmaxf(m, gm);
            float r  = __expf(m - mn);
            float e0 = __expf(sp0 - mn);
            float e1 = __expf(sp1 - mn);
            float e2 = __expf(sp2 - mn);
            float e3 = __expf(sp3 - mn);
            ax = ax * r + e0 * X[0].x + e1 * X[1].x + e2 * X[2].x + e3 * X[3].x;
            ay = ay * r + e0 * X[0].y + e1 * X[1].y + e2 * X[2].y + e3 * X[3].y;
            az = az * r + e0 * X[0].z + e1 * X[1].z + e2 * X[2].z + e3 * X[3].z;
            aw = aw * r + e0 * X[0].w + e1 * X[1].w + e2 * X[2].w + e3 * X[3].w;
            den = den * r + e0 + e1 + e2 + e3;
            m = mn;

#pragma unroll
            for (int u = 0; u < 4; u++) { A[u] = An[u]; Bv[u] = Bn[u]; }
        }
    }

    // remainder (<=3 edges)
    for (; j < end; j++) {
        float4 A = rec[2 * (size_t)j];
        float4 B = rec[2 * (size_t)j + 1];
        float4 X = *(const float4*)(g_xl + (size_t)__float_as_int(A.x) * HIDN + ch);
        float sp = edge_score(A, B, X);
#pragma unroll
        for (int off = 1; off <= 4; off <<= 1)
            sp += __shfl_xor_sync(0xffffffffu, sp, off);
        float mn = fmaxf(m, sp);
        float r  = __expf(m - mn);
        float wg = __expf(sp - mn);
        ax = ax * r + wg * X.x;
        ay = ay * r + wg * X.y;
        az = az * r + wg * X.z;
        aw = aw * r + wg * X.w;
        den = den * r + wg;
        m = mn;
    }

    float inv = 1.0f / den;
    float4 o;
    o.x = ax * inv + bc.x;
    o.y = ay * inv + bc.y;
    o.z = az * inv + bc.z;
    o.w = aw * inv + bc.w;
    *(float4*)(g_conv + (size_t)node * HIDN + ch) = o;

    // BN stats: per-warp slabs, then block reduce + global atomics
    *(float4*)&s_sum[wid][ch] = o;
    *(float4*)&s_sq[wid][ch] = make_float4(o.x * o.x, o.y * o.y, o.z * o.z, o.w * o.w);
    __syncthreads();
    int t = threadIdx.x;
    if (t < HIDN) {
        float s = 0.f, q = 0.f;
#pragma unroll
        for (int w = 0; w < 8; w++) { s += s_sum[w][t]; q += s_sq[w][t]; }
        atomicAdd(&g_stats[l * 2 * HIDN + t], s);
        atomicAdd(&g_stats[l * 2 * HIDN + HIDN + t], q);
    }
}

// ---------------- batchnorm apply (+ residual) + relu + bf16 split ----------
__global__ void k_bnapply(const float* __restrict__ gamma_l, const float* __restrict__ beta_l,
                          const float* __restrict__ res, float* __restrict__ out, int l) {
    int j4 = blockIdx.x * blockDim.x + threadIdx.x;   // one float4 per thread
    if (j4 >= NN * HIDN / 4) return;
    int f4 = (j4 & 31);                                // float4-index within feature dim
    const float invN = 1.0f / (float)NN;

    float4 sum4 = ((const float4*)(g_stats + l * 2 * HIDN))[f4];
    float4 sq4  = ((const float4*)(g_stats + l * 2 * HIDN + HIDN))[f4];
    float4 gm = ((const float4*)gamma_l)[f4];
    float4 bt = ((const float4*)beta_l)[f4];
    float4 c = ((const float4*)g_conv)[j4];

    float4 y;
    {
        float mean = sum4.x * invN, var = sq4.x * invN - mean * mean;
        y.x = gm.x * (c.x - mean) * rsqrtf(var + 1e-5f) + bt.x;
        mean = sum4.y * invN; var = sq4.y * invN - mean * mean;
        y.y = gm.y * (c.y - mean) * rsqrtf(var + 1e-5f) + bt.y;
        mean = sum4.z * invN; var = sq4.z * invN - mean * mean;
        y.z = gm.z * (c.z - mean) * rsqrtf(var + 1e-5f) + bt.z;
        mean = sum4.w * invN; var = sq4.w * invN - mean * mean;
        y.w = gm.w * (c.w - mean) * rsqrtf(var + 1e-5f) + bt.w;
    }
    if (res) {
        float4 r4 = ((const float4*)res)[j4];
        y.x += r4.x; y.y += r4.y; y.z += r4.z; y.w += r4.w;
    }
    y.x = fmaxf(y.x, 0.f); y.y = fmaxf(y.y, 0.f);
    y.z = fmaxf(y.z, 0.f); y.w = fmaxf(y.w, 0.f);
    ((float4*)out)[j4] = y;

    __nv_bfloat16 h0, l0, h1, l1, h2, l2, h3, l3;
    bf_split(y.x, h0, l0); bf_split(y.y, h1, l1);
    bf_split(y.z, h2, l2); bf_split(y.w, h3, l3);
    ((__nv_bfloat162*)g_h_hi)[j4 * 2]     = __nv_bfloat162(h0, h1);
    ((__nv_bfloat162*)g_h_hi)[j4 * 2 + 1] = __nv_bfloat162(h2, h3);
    ((__nv_bfloat162*)g_h_lo)[j4 * 2]     = __nv_bfloat162(l0, l1);
    ((__nv_bfloat162*)g_h_lo)[j4 * 2 + 1] = __nv_bfloat162(l2, l3);
}

// ---------------- mean pooling per graph -----------------------------------
__global__ void k_pool(const int* __restrict__ batch) {
    int idx = blockIdx.x * blockDim.x + threadIdx.x;
    int stride = gridDim.x * blockDim.x;
    for (int j = idx; j < NN * HIDN; j += stride) {
        int n = j >> 7;
        int f = j & (HIDN - 1);
        atomicAdd(&g_pooled[batch[n] * HIDN + f], g_bufA[j]);
    }
    for (int j = idx; j < NN; j += stride)
        atomicAdd(&g_gcnt[batch[j]], 1.0f);
}

// ---------------- final MLP: relu(pooled@W1+b1)@W2+b2 ----------------------
__global__ void k_mlp(const float* __restrict__ W1, const float* __restrict__ b1,
                      const float* __restrict__ W2, const float* __restrict__ b2,
                      float* __restrict__ out) {
    __shared__ float pl[HIDN];
    __shared__ float hid[64];
    int g = blockIdx.x;
    int t = threadIdx.x;
    float inv = 1.0f / fmaxf(g_gcnt[g], 1.0f);
    for (int j = t; j < HIDN; j += 64) pl[j] = g_pooled[g * HIDN + j] * inv;
    __syncthreads();
    float a = b1[t];
    for (int k = 0; k < HIDN; k++) a += pl[k] * W1[k * 64 + t];
    hid[t] = fmaxf(a, 0.f);
    __syncthreads();
    if (t < 3) {
        float lg = b2[t];
        for (int k = 0; k < 64; k++) lg += hid[k] * W2[k * 3 + t];
        out[g * 3 + t] = lg;
    }
}

// ---------------- launch ----------------------------------------------------
extern "C" void kernel_launch(void* const* d_in, const int* in_sizes, int n_in,
                              void* d_out, int out_size) {
    const float* x     = (const float*)d_in[0];
    const int*   ei    = (const int*)d_in[1];
    const float* ea    = (const float*)d_in[2];
    const int*   batch = (const int*)d_in[3];
    const float* Win   = (const float*)d_in[4];
    const float* b_in  = (const float*)d_in[5];
    const float* Wl    = (const float*)d_in[6];
    const float* bl    = (const float*)d_in[7];
    const float* Wr    = (const float*)d_in[8];
    const float* br    = (const float*)d_in[9];
    const float* We    = (const float*)d_in[10];
    const float* att   = (const float*)d_in[11];
    const float* bconv = (const float*)d_in[12];
    const float* gamma = (const float*)d_in[13];
    const float* beta  = (const float*)d_in[14];
    const float* W1    = (const float*)d_in[15];
    const float* b1    = (const float*)d_in[16];
    const float* W2    = (const float*)d_in[17];
    const float* b2    = (const float*)d_in[18];
    float* out = (float*)d_out;

    float* bufA = nullptr;
    float* bufB = nullptr;
    cudaGetSymbolAddress((void**)&bufA, g_bufA);
    cudaGetSymbolAddress((void**)&bufB, g_bufB);
    __nv_bfloat16* whi = nullptr;
    __nv_bfloat16* wlo = nullptr;
    cudaGetSymbolAddress((void**)&whi, g_w_hi);
    cudaGetSymbolAddress((void**)&wlo, g_w_lo);

    k_init<<<64, 256>>>();
    k_wsplit<<<(NLAY * 2 * HIDN * HIDN + 255) / 256, 256>>>(Wl, Wr);
    k_deg<<<(EE + 255) / 256, 256>>>(ei);
    k_scan<<<1, 1024>>>();
    k_scatter<<<(EF + 255) / 256, 256>>>(ei, ea);
    k_loopattr<<<NN / 8, 256>>>();
    k_ingemm<<<NN, HIDN>>>(x, Win, b_in);

    dim3 ggrid(NN / 128, 2, 2);
    for (int l = 0; l < NLAY; l++) {
        float* outb      = (l % 2 == 0) ? bufB : bufA;
        const float* res = (l % 2 == 0) ? nullptr : bufA;

        k_gemm_bf16<<<ggrid, 128>>>(whi + (size_t)l * 2 * HIDN * HIDN,
                                    wlo + (size_t)l * 2 * HIDN * HIDN,
                                    bl + (size_t)l * HIDN, br + (size_t)l * HIDN);
        k_fused<<<NN / 8, 256>>>(We + (size_t)l * EDIM * HIDN,
                                 att + (size_t)l * NHEAD * HC,
                                 bconv + (size_t)l * HIDN, l);
        k_bnapply<<<NN * HIDN / 4 / 256, 256>>>(gamma + (size_t)l * HIDN,
                                                beta + (size_t)l * HIDN,
                                                res, outb, l);
    }

    k_pool<<<1024, 256>>>(batch);
    k_mlp<<<GG, 64>>>(W1, b1, W2, b2, out);
}